// round 3
// baseline (speedup 1.0000x reference)
#include <cuda_runtime.h>
#include <math.h>

// Problem constants
#define BATCH   4
#define SEQ     2048
#define DMODEL  1024
#define NHEADS  16
#define DHEAD   64
#define MROWS   (BATCH * SEQ)   // 8192

// -------------------- scratch (device globals; no allocation) --------------------
__device__ float g_Q[(size_t)MROWS * DMODEL];
__device__ float g_K[(size_t)MROWS * DMODEL];
__device__ float g_V[(size_t)MROWS * DMODEL];
__device__ float g_O[(size_t)MROWS * DMODEL];

// -------------------- GEMM: C[M,N] = A[M,K] @ W[K,N] + bias[N] --------------------
// 128x128 block tile, BK=16, 256 threads, 8x8 microtile.
#define GBM 128
#define GBN 128
#define GBK 16

__global__ __launch_bounds__(256, 2)
void gemm_bias_kernel(const float* __restrict__ A, const float* __restrict__ W,
                      const float* __restrict__ bias, float* __restrict__ C,
                      int M, int N, int K) {
    __shared__ float As[GBK][GBM];   // transposed A tile
    __shared__ float Bs[GBK][GBN];

    const int tid = threadIdx.x;
    const int tx = tid % 16;
    const int ty = tid / 16;
    const int bm = blockIdx.y * GBM;
    const int bn = blockIdx.x * GBN;

    float acc[8][8];
#pragma unroll
    for (int i = 0; i < 8; i++)
#pragma unroll
        for (int j = 0; j < 8; j++) acc[i][j] = 0.f;

    // A loader mapping: kg4 = tid%4 (which float4 along k), m = tid/4 (row), +64 second iter
    const int a_kg4 = (tid % 4) * 4;
    const int a_m   = tid / 4;       // 0..63
    // B loader mapping: n4 = (tid%32)*4, k = tid/32 (0..7), +8 second iter
    const int b_n4 = (tid % 32) * 4;
    const int b_k  = tid / 32;

    for (int k0 = 0; k0 < K; k0 += GBK) {
        // ---- load A tile (transposed into As[k][m]) ----
#pragma unroll
        for (int it = 0; it < 2; it++) {
            int m = a_m + it * 64;
            float4 av = *(const float4*)&A[(size_t)(bm + m) * K + k0 + a_kg4];
            As[a_kg4 + 0][m] = av.x;
            As[a_kg4 + 1][m] = av.y;
            As[a_kg4 + 2][m] = av.z;
            As[a_kg4 + 3][m] = av.w;
        }
        // ---- load B tile ----
#pragma unroll
        for (int it = 0; it < 2; it++) {
            int kk = b_k + it * 8;
            *(float4*)&Bs[kk][b_n4] =
                *(const float4*)&W[(size_t)(k0 + kk) * N + bn + b_n4];
        }
        __syncthreads();

#pragma unroll
        for (int kk = 0; kk < GBK; kk++) {
            float a_frag[8], b_frag[8];
            *(float4*)&a_frag[0] = *(const float4*)&As[kk][ty * 4];
            *(float4*)&a_frag[4] = *(const float4*)&As[kk][64 + ty * 4];
            *(float4*)&b_frag[0] = *(const float4*)&Bs[kk][tx * 4];
            *(float4*)&b_frag[4] = *(const float4*)&Bs[kk][64 + tx * 4];
#pragma unroll
            for (int i = 0; i < 8; i++)
#pragma unroll
                for (int j = 0; j < 8; j++)
                    acc[i][j] += a_frag[i] * b_frag[j];
        }
        __syncthreads();
    }

    // ---- epilogue: bias + store (rows {ty*4+i, 64+ty*4+i}, cols {tx*4+j, 64+tx*4+j}) ----
    const int c0 = bn + tx * 4;
    const int c1 = bn + 64 + tx * 4;
    float4 bia0 = *(const float4*)&bias[c0];
    float4 bia1 = *(const float4*)&bias[c1];
#pragma unroll
    for (int i = 0; i < 8; i++) {
        int r = bm + ((i < 4) ? (ty * 4 + i) : (64 + ty * 4 + (i - 4)));
        float4 o0, o1;
        o0.x = acc[i][0] + bia0.x; o0.y = acc[i][1] + bia0.y;
        o0.z = acc[i][2] + bia0.z; o0.w = acc[i][3] + bia0.w;
        o1.x = acc[i][4] + bia1.x; o1.y = acc[i][5] + bia1.y;
        o1.z = acc[i][6] + bia1.z; o1.w = acc[i][7] + bia1.w;
        *(float4*)&C[(size_t)r * N + c0] = o0;
        *(float4*)&C[(size_t)r * N + c1] = o1;
    }
}

// -------------------- flash attention (fp32, online softmax) --------------------
// grid: (SEQ/128, NHEADS, BATCH). 128 threads; each thread owns one query row.
// Q/K/V/O are flat [B*S, DMODEL]; head h occupies columns [h*64, h*64+64).
#define AT_BM 128
#define AT_TN 64
#define QPAD  68   // smem row stride for strided-row phases (avoids 32-way conflicts)

__global__ __launch_bounds__(128, 2)
void attention_kernel(const float* __restrict__ Q, const float* __restrict__ K,
                      const float* __restrict__ V, float* __restrict__ O) {
    __shared__ float smem[AT_BM * QPAD];   // 34 KB: Q staging / K+V tiles / O staging

    const int t  = threadIdx.x;
    const int qb = blockIdx.x;
    const int h  = blockIdx.y;
    const int b  = blockIdx.z;

    const size_t row0 = (size_t)b * SEQ + (size_t)qb * AT_BM;
    const int hd = h * DHEAD;

    // ---- phase 1: stage Q tile, copy own row to registers ----
    for (int i = t; i < AT_BM * 16; i += 128) {
        int r = i >> 4, d4 = (i & 15) << 2;
        float4 qv = *(const float4*)&Q[(row0 + r) * DMODEL + hd + d4];
        *(float4*)&smem[r * QPAD + d4] = qv;
    }
    __syncthreads();
    float q[DHEAD];
#pragma unroll
    for (int d4 = 0; d4 < 16; d4++) {
        float4 v4 = *(const float4*)&smem[t * QPAD + d4 * 4];
        q[d4 * 4 + 0] = v4.x; q[d4 * 4 + 1] = v4.y;
        q[d4 * 4 + 2] = v4.z; q[d4 * 4 + 3] = v4.w;
    }
    __syncthreads();

    float* Ks = smem;                    // [64][64]
    float* Vs = smem + AT_TN * DHEAD;    // [64][64]

    float o[DHEAD];
#pragma unroll
    for (int d = 0; d < DHEAD; d++) o[d] = 0.f;
    float m = -1e30f, l = 0.f;
    const float scale = 0.125f;          // 1/sqrt(64)

    for (int kt = 0; kt < SEQ; kt += AT_TN) {
        // ---- load K,V tiles (coalesced float4) ----
        for (int i = t; i < AT_TN * 16; i += 128) {
            int r = i >> 4, d4 = (i & 15) << 2;
            size_t g = ((size_t)b * SEQ + kt + r) * DMODEL + hd + d4;
            *(float4*)&Ks[r * DHEAD + d4] = *(const float4*)&K[g];
            *(float4*)&Vs[r * DHEAD + d4] = *(const float4*)&V[g];
        }
        __syncthreads();

#pragma unroll 1
        for (int j = 0; j < AT_TN; j++) {
            // dot(q, K[j]) with 4 partial chains to break FFMA latency
            const float4* kr = (const float4*)&Ks[j * DHEAD];
            float s0 = 0.f, s1 = 0.f, s2 = 0.f, s3 = 0.f;
#pragma unroll
            for (int d4 = 0; d4 < 16; d4++) {
                float4 k4 = kr[d4];
                s0 += q[d4 * 4 + 0] * k4.x;
                s1 += q[d4 * 4 + 1] * k4.y;
                s2 += q[d4 * 4 + 2] * k4.z;
                s3 += q[d4 * 4 + 3] * k4.w;
            }
            float s = ((s0 + s1) + (s2 + s3)) * scale;

            if (s > m) {                  // new running max: rescale (log-rare)
                float corr = __expf(m - s);
                l *= corr;
#pragma unroll
                for (int d = 0; d < DHEAD; d++) o[d] *= corr;
                m = s;
            }
            float p = __expf(s - m);
            l += p;

            const float4* vr = (const float4*)&Vs[j * DHEAD];
#pragma unroll
            for (int d4 = 0; d4 < 16; d4++) {
                float4 v4 = vr[d4];
                o[d4 * 4 + 0] += p * v4.x;
                o[d4 * 4 + 1] += p * v4.y;
                o[d4 * 4 + 2] += p * v4.z;
                o[d4 * 4 + 3] += p * v4.w;
            }
        }
        __syncthreads();
    }

    // ---- phase 3: normalize, stage to smem, coalesced store ----
    float inv = 1.f / l;
#pragma unroll
    for (int d4 = 0; d4 < 16; d4++) {
        float4 ov;
        ov.x = o[d4 * 4 + 0] * inv; ov.y = o[d4 * 4 + 1] * inv;
        ov.z = o[d4 * 4 + 2] * inv; ov.w = o[d4 * 4 + 3] * inv;
        *(float4*)&smem[t * QPAD + d4 * 4] = ov;
    }
    __syncthreads();
    for (int i = t; i < AT_BM * 16; i += 128) {
        int r = i >> 4, d4 = (i & 15) << 2;
        float4 ov = *(const float4*)&smem[r * QPAD + d4];
        *(float4*)&O[(row0 + r) * DMODEL + hd + d4] = ov;
    }
}

// -------------------- launch --------------------
extern "C" void kernel_launch(void* const* d_in, const int* in_sizes, int n_in,
                              void* d_out, int out_size) {
    // metadata order: v, k, q, wq, bq, wk, bk, wv, bv, wo, bo
    const float* v  = (const float*)d_in[0];
    const float* k  = (const float*)d_in[1];
    const float* q  = (const float*)d_in[2];
    const float* wq = (const float*)d_in[3];
    const float* bq = (const float*)d_in[4];
    const float* wk = (const float*)d_in[5];
    const float* bk = (const float*)d_in[6];
    const float* wv = (const float*)d_in[7];
    const float* bv = (const float*)d_in[8];
    const float* wo = (const float*)d_in[9];
    const float* bo = (const float*)d_in[10];
    float* out = (float*)d_out;

    float* Qf; cudaGetSymbolAddress((void**)&Qf, g_Q);
    float* Kf; cudaGetSymbolAddress((void**)&Kf, g_K);
    float* Vf; cudaGetSymbolAddress((void**)&Vf, g_V);
    float* Of; cudaGetSymbolAddress((void**)&Of, g_O);

    dim3 ggrid(DMODEL / GBN, MROWS / GBM);   // (8, 64)
    dim3 gblk(256);

    gemm_bias_kernel<<<ggrid, gblk>>>(q, wq, bq, Qf, MROWS, DMODEL, DMODEL);
    gemm_bias_kernel<<<ggrid, gblk>>>(k, wk, bk, Kf, MROWS, DMODEL, DMODEL);
    gemm_bias_kernel<<<ggrid, gblk>>>(v, wv, bv, Vf, MROWS, DMODEL, DMODEL);

    dim3 agrid(SEQ / AT_BM, NHEADS, BATCH);  // (16, 16, 4)
    attention_kernel<<<agrid, 128>>>(Qf, Kf, Vf, Of);

    gemm_bias_kernel<<<ggrid, gblk>>>(Of, wo, bo, out, MROWS, DMODEL, DMODEL);
}

// round 6
// speedup vs baseline: 1.2528x; 1.2528x over previous
#include <cuda_runtime.h>
#include <cuda_bf16.h>
#include <cstdint>
#include <math.h>

// Problem constants
#define BATCH   4
#define SEQ     2048
#define DMODEL  1024
#define NHEADS  16
#define DHEAD   64
#define MROWS   (BATCH * SEQ)   // 8192

// -------------------- scratch (device globals; no allocation) --------------------
__device__ float g_Q[(size_t)MROWS * DMODEL];
__device__ float g_K[(size_t)MROWS * DMODEL];
__device__ float g_V[(size_t)MROWS * DMODEL];
__device__ float g_O[(size_t)MROWS * DMODEL];
__device__ __nv_bfloat16 g_Ahi[(size_t)MROWS * DMODEL];
__device__ __nv_bfloat16 g_Alo[(size_t)MROWS * DMODEL];
__device__ __nv_bfloat16 g_Whi[(size_t)DMODEL * DMODEL];
__device__ __nv_bfloat16 g_Wlo[(size_t)DMODEL * DMODEL];

// ==================== small PTX helpers (all base-sm_103 legal) ====================
__device__ __forceinline__ uint32_t smem_u32(const void* p) {
    uint32_t a;
    asm("{ .reg .u64 t; cvta.to.shared.u64 t, %1; cvt.u32.u64 %0, t; }" : "=r"(a) : "l"(p));
    return a;
}
__device__ __forceinline__ void cpa16(uint32_t s, const void* g) {
    asm volatile("cp.async.cg.shared.global [%0], [%1], 16;" :: "r"(s), "l"(g));
}
__device__ __forceinline__ void cpa_commit() {
    asm volatile("cp.async.commit_group;" ::: "memory");
}
__device__ __forceinline__ void ldsm_x4(uint32_t& r0, uint32_t& r1, uint32_t& r2, uint32_t& r3,
                                        uint32_t addr) {
    asm volatile("ldmatrix.sync.aligned.m8n8.x4.shared.b16 {%0,%1,%2,%3}, [%4];"
                 : "=r"(r0), "=r"(r1), "=r"(r2), "=r"(r3) : "r"(addr));
}
__device__ __forceinline__ void mma16816(float* d, const uint32_t* a, const uint32_t* b) {
    asm volatile(
        "mma.sync.aligned.m16n8k16.row.col.f32.bf16.bf16.f32 "
        "{%0,%1,%2,%3}, {%4,%5,%6,%7}, {%8,%9}, {%0,%1,%2,%3};"
        : "+f"(d[0]), "+f"(d[1]), "+f"(d[2]), "+f"(d[3])
        : "r"(a[0]), "r"(a[1]), "r"(a[2]), "r"(a[3]), "r"(b[0]), "r"(b[1]));
}

// ==================== pre-pass: fp32 -> bf16 hi/lo split ====================
__global__ __launch_bounds__(256)
void split_kernel(const float* __restrict__ in, __nv_bfloat16* __restrict__ hi,
                  __nv_bfloat16* __restrict__ lo, int n4) {
    int i = blockIdx.x * blockDim.x + threadIdx.x;
    if (i >= n4) return;
    float4 v = ((const float4*)in)[i];
    float vv[4] = {v.x, v.y, v.z, v.w};
    __nv_bfloat16 h[4], l[4];
#pragma unroll
    for (int j = 0; j < 4; j++) {
        h[j] = __float2bfloat16(vv[j]);
        l[j] = __float2bfloat16(vv[j] - __bfloat162float(h[j]));
    }
    ((uint2*)hi)[i] = *(uint2*)h;
    ((uint2*)lo)[i] = *(uint2*)l;
}

// ==================== pre-pass: W[K,N] -> WT[N,K] bf16 hi/lo ====================
__global__ __launch_bounds__(256)
void trans_split_kernel(const float* __restrict__ W, __nv_bfloat16* __restrict__ hi,
                        __nv_bfloat16* __restrict__ lo) {
    __shared__ float tile[32][33];
    const int tx = threadIdx.x & 31, tyo = threadIdx.x >> 5;   // 32x8
    const int x = blockIdx.x * 32 + tx;
    const int y0 = blockIdx.y * 32;
#pragma unroll
    for (int r = tyo; r < 32; r += 8)
        tile[r][tx] = W[(size_t)(y0 + r) * DMODEL + x];
    __syncthreads();
    const int n0 = blockIdx.x * 32;
    const int k  = y0 + tx;
#pragma unroll
    for (int r = tyo; r < 32; r += 8) {
        float v = tile[tx][r];
        __nv_bfloat16 h = __float2bfloat16(v);
        __nv_bfloat16 l = __float2bfloat16(v - __bfloat162float(h));
        hi[(size_t)(n0 + r) * DMODEL + k] = h;
        lo[(size_t)(n0 + r) * DMODEL + k] = l;
    }
}

// ==================== mma.sync GEMM: C[M,N] = A @ W + bias (bf16 x 3 passes) ====
// CTA 128x128, BK=32, 256 threads = 8 warps (4 along M x 2 along N).
// Warp tile 32x64 -> 2 m16 tiles x 8 n8 tiles, fp32 accumulators.
// SMEM rows padded to 40 bf16 (80B) -> conflict-free ldmatrix.
#define BM 128
#define BN 128
#define BK 32
#define PADB 80                    // padded row bytes (40 bf16)
#define TILE_B (128 * PADB)        // 10240 B per array
#define STAGE_B (4 * TILE_B)       // Ahi, Alo, Bhi, Blo
#define GEMM_DYN_SMEM (2 * STAGE_B) // 81920
#define NCHUNK (DMODEL / BK)       // 32

__global__ __launch_bounds__(256)
void gemm_mma_kernel(const __nv_bfloat16* __restrict__ Ahi, const __nv_bfloat16* __restrict__ Alo,
                     const __nv_bfloat16* __restrict__ Bhi, const __nv_bfloat16* __restrict__ Blo,
                     const float* __restrict__ bias, float* __restrict__ C) {
    extern __shared__ char smem[];
    const uint32_t sb = smem_u32(smem);
    const int t = threadIdx.x;
    const int lane = t & 31;
    const int wid  = t >> 5;
    const int wm   = wid & 3;      // 0..3 -> 32-row band
    const int wn   = wid >> 2;     // 0..1 -> 64-col band
    const int m0 = blockIdx.y * BM;
    const int n0 = blockIdx.x * BN;

    // per-lane ldmatrix address offsets (bytes, within a tile array)
    const uint32_t a_off = (uint32_t)((wm * 32 + (lane & 15)) * PADB + (lane >> 4) * 16);
    const uint32_t b_off = (uint32_t)((wn * 64 + ((lane >> 4) & 1) * 8 + (lane & 7)) * PADB
                                      + ((lane >> 3) & 1) * 16);

    // stage loader: 4 arrays x 512 16B chunks, 2 chunks/thread/array
    auto load_stage = [&](int c, int s) {
        const uint32_t st = sb + (uint32_t)s * STAGE_B;
        const int k0 = c * BK;
#pragma unroll
        for (int h = 0; h < 2; h++) {
            int idx = t + h * 256;
            int row = idx >> 2, cc = idx & 3;
            uint32_t so = (uint32_t)(row * PADB + cc * 16);
            size_t ga = (size_t)(m0 + row) * DMODEL + k0 + cc * 8;
            size_t gb = (size_t)(n0 + row) * DMODEL + k0 + cc * 8;
            cpa16(st + 0 * TILE_B + so, Ahi + ga);
            cpa16(st + 1 * TILE_B + so, Alo + ga);
            cpa16(st + 2 * TILE_B + so, Bhi + gb);
            cpa16(st + 3 * TILE_B + so, Blo + gb);
        }
        cpa_commit();
    };

    float acc[2][8][4];
#pragma unroll
    for (int i = 0; i < 2; i++)
#pragma unroll
        for (int j = 0; j < 8; j++)
#pragma unroll
            for (int r = 0; r < 4; r++) acc[i][j][r] = 0.f;

    load_stage(0, 0);

    for (int c = 0; c < NCHUNK; c++) {
        if (c + 1 < NCHUNK) {
            load_stage(c + 1, (c + 1) & 1);
            asm volatile("cp.async.wait_group 1;" ::: "memory");
        } else {
            asm volatile("cp.async.wait_group 0;" ::: "memory");
        }
        __syncthreads();

        const uint32_t st = sb + (uint32_t)(c & 1) * STAGE_B;
#pragma unroll
        for (int ks = 0; ks < BK; ks += 16) {
            uint32_t aH[2][4], aL[2][4], bH[4][4], bL[4][4];
#pragma unroll
            for (int mt = 0; mt < 2; mt++) {
                uint32_t ad = st + a_off + (uint32_t)(mt * 16 * PADB + ks * 2);
                ldsm_x4(aH[mt][0], aH[mt][1], aH[mt][2], aH[mt][3], ad + 0 * TILE_B);
                ldsm_x4(aL[mt][0], aL[mt][1], aL[mt][2], aL[mt][3], ad + 1 * TILE_B);
            }
#pragma unroll
            for (int jp = 0; jp < 4; jp++) {
                uint32_t bd = st + b_off + (uint32_t)(jp * 16 * PADB + ks * 2);
                ldsm_x4(bH[jp][0], bH[jp][1], bH[jp][2], bH[jp][3], bd + 2 * TILE_B);
                ldsm_x4(bL[jp][0], bL[jp][1], bL[jp][2], bL[jp][3], bd + 3 * TILE_B);
            }
            // pass 1: hi*hi, pass 2: hi*lo, pass 3: lo*hi  (lo*lo dropped, ~2^-17)
#pragma unroll
            for (int mt = 0; mt < 2; mt++)
#pragma unroll
                for (int jp = 0; jp < 4; jp++) {
                    mma16816(acc[mt][jp * 2 + 0], aH[mt], &bH[jp][0]);
                    mma16816(acc[mt][jp * 2 + 1], aH[mt], &bH[jp][2]);
                    mma16816(acc[mt][jp * 2 + 0], aH[mt], &bL[jp][0]);
                    mma16816(acc[mt][jp * 2 + 1], aH[mt], &bL[jp][2]);
                    mma16816(acc[mt][jp * 2 + 0], aL[mt], &bH[jp][0]);
                    mma16816(acc[mt][jp * 2 + 1], aL[mt], &bH[jp][2]);
                }
        }
        __syncthreads();
    }

    // -------- epilogue: acc + bias -> C (fp32) --------
    const int gid = lane >> 2, tig = lane & 3;
#pragma unroll
    for (int mt = 0; mt < 2; mt++) {
        const int r0 = m0 + wm * 32 + mt * 16 + gid;
#pragma unroll
        for (int j = 0; j < 8; j++) {
            const int col = n0 + wn * 64 + j * 8 + tig * 2;
            const float bx = bias[col], by = bias[col + 1];
            float2 v0, v1;
            v0.x = acc[mt][j][0] + bx; v0.y = acc[mt][j][1] + by;
            v1.x = acc[mt][j][2] + bx; v1.y = acc[mt][j][3] + by;
            *(float2*)&C[(size_t)r0 * DMODEL + col]       = v0;
            *(float2*)&C[(size_t)(r0 + 8) * DMODEL + col] = v1;
        }
    }
}

// -------------------- flash attention (fp32, online softmax) --------------------
#define AT_BM 128
#define AT_TN 64
#define QPAD  68

__global__ __launch_bounds__(128, 2)
void attention_kernel(const float* __restrict__ Q, const float* __restrict__ K,
                      const float* __restrict__ V, float* __restrict__ O) {
    __shared__ float smem[AT_BM * QPAD];

    const int t  = threadIdx.x;
    const int qb = blockIdx.x;
    const int h  = blockIdx.y;
    const int b  = blockIdx.z;

    const size_t row0 = (size_t)b * SEQ + (size_t)qb * AT_BM;
    const int hd = h * DHEAD;

    for (int i = t; i < AT_BM * 16; i += 128) {
        int r = i >> 4, d4 = (i & 15) << 2;
        float4 qv = *(const float4*)&Q[(row0 + r) * DMODEL + hd + d4];
        *(float4*)&smem[r * QPAD + d4] = qv;
    }
    __syncthreads();
    float q[DHEAD];
#pragma unroll
    for (int d4 = 0; d4 < 16; d4++) {
        float4 v4 = *(const float4*)&smem[t * QPAD + d4 * 4];
        q[d4 * 4 + 0] = v4.x; q[d4 * 4 + 1] = v4.y;
        q[d4 * 4 + 2] = v4.z; q[d4 * 4 + 3] = v4.w;
    }
    __syncthreads();

    float* Ks = smem;
    float* Vs = smem + AT_TN * DHEAD;

    float o[DHEAD];
#pragma unroll
    for (int d = 0; d < DHEAD; d++) o[d] = 0.f;
    float m = -1e30f, l = 0.f;
    const float scale = 0.125f;

    for (int kt = 0; kt < SEQ; kt += AT_TN) {
        for (int i = t; i < AT_TN * 16; i += 128) {
            int r = i >> 4, d4 = (i & 15) << 2;
            size_t g = ((size_t)b * SEQ + kt + r) * DMODEL + hd + d4;
            *(float4*)&Ks[r * DHEAD + d4] = *(const float4*)&K[g];
            *(float4*)&Vs[r * DHEAD + d4] = *(const float4*)&V[g];
        }
        __syncthreads();

#pragma unroll 1
        for (int j = 0; j < AT_TN; j++) {
            const float4* kr = (const float4*)&Ks[j * DHEAD];
            float s0 = 0.f, s1 = 0.f, s2 = 0.f, s3 = 0.f;
#pragma unroll
            for (int d4 = 0; d4 < 16; d4++) {
                float4 k4 = kr[d4];
                s0 += q[d4 * 4 + 0] * k4.x;
                s1 += q[d4 * 4 + 1] * k4.y;
                s2 += q[d4 * 4 + 2] * k4.z;
                s3 += q[d4 * 4 + 3] * k4.w;
            }
            float s = ((s0 + s1) + (s2 + s3)) * scale;

            if (s > m) {
                float corr = __expf(m - s);
                l *= corr;
#pragma unroll
                for (int d = 0; d < DHEAD; d++) o[d] *= corr;
                m = s;
            }
            float p = __expf(s - m);
            l += p;

            const float4* vr = (const float4*)&Vs[j * DHEAD];
#pragma unroll
            for (int d4 = 0; d4 < 16; d4++) {
                float4 v4 = vr[d4];
                o[d4 * 4 + 0] += p * v4.x;
                o[d4 * 4 + 1] += p * v4.y;
                o[d4 * 4 + 2] += p * v4.z;
                o[d4 * 4 + 3] += p * v4.w;
            }
        }
        __syncthreads();
    }

    float inv = 1.f / l;
#pragma unroll
    for (int d4 = 0; d4 < 16; d4++) {
        float4 ov;
        ov.x = o[d4 * 4 + 0] * inv; ov.y = o[d4 * 4 + 1] * inv;
        ov.z = o[d4 * 4 + 2] * inv; ov.w = o[d4 * 4 + 3] * inv;
        *(float4*)&smem[t * QPAD + d4 * 4] = ov;
    }
    __syncthreads();
    for (int i = t; i < AT_BM * 16; i += 128) {
        int r = i >> 4, d4 = (i & 15) << 2;
        float4 ov = *(const float4*)&smem[r * QPAD + d4];
        *(float4*)&O[(row0 + r) * DMODEL + hd + d4] = ov;
    }
}

// -------------------- launch --------------------
extern "C" void kernel_launch(void* const* d_in, const int* in_sizes, int n_in,
                              void* d_out, int out_size) {
    // metadata order: v, k, q, wq, bq, wk, bk, wv, bv, wo, bo
    const float* v  = (const float*)d_in[0];
    const float* k  = (const float*)d_in[1];
    const float* q  = (const float*)d_in[2];
    const float* wq = (const float*)d_in[3];
    const float* bq = (const float*)d_in[4];
    const float* wk = (const float*)d_in[5];
    const float* bk = (const float*)d_in[6];
    const float* wv = (const float*)d_in[7];
    const float* bv = (const float*)d_in[8];
    const float* wo = (const float*)d_in[9];
    const float* bo = (const float*)d_in[10];
    float* out = (float*)d_out;

    float* Qf; cudaGetSymbolAddress((void**)&Qf, g_Q);
    float* Kf; cudaGetSymbolAddress((void**)&Kf, g_K);
    float* Vf; cudaGetSymbolAddress((void**)&Vf, g_V);
    float* Of; cudaGetSymbolAddress((void**)&Of, g_O);
    __nv_bfloat16* Ahi; cudaGetSymbolAddress((void**)&Ahi, g_Ahi);
    __nv_bfloat16* Alo; cudaGetSymbolAddress((void**)&Alo, g_Alo);
    __nv_bfloat16* Whi; cudaGetSymbolAddress((void**)&Whi, g_Whi);
    __nv_bfloat16* Wlo; cudaGetSymbolAddress((void**)&Wlo, g_Wlo);

    cudaFuncSetAttribute(gemm_mma_kernel,
                         cudaFuncAttributeMaxDynamicSharedMemorySize, GEMM_DYN_SMEM);

    const int N4 = MROWS * DMODEL / 4;
    const dim3 tgrid(32, 32);
    const dim3 ggrid(DMODEL / BN, MROWS / BM);   // (8, 64)

    // Q = q @ wq + bq
    split_kernel<<<(N4 + 255) / 256, 256>>>(q, Ahi, Alo, N4);
    trans_split_kernel<<<tgrid, 256>>>(wq, Whi, Wlo);
    gemm_mma_kernel<<<ggrid, 256, GEMM_DYN_SMEM>>>(Ahi, Alo, Whi, Wlo, bq, Qf);
    // K = k @ wk + bk
    split_kernel<<<(N4 + 255) / 256, 256>>>(k, Ahi, Alo, N4);
    trans_split_kernel<<<tgrid, 256>>>(wk, Whi, Wlo);
    gemm_mma_kernel<<<ggrid, 256, GEMM_DYN_SMEM>>>(Ahi, Alo, Whi, Wlo, bk, Kf);
    // V = v @ wv + bv
    split_kernel<<<(N4 + 255) / 256, 256>>>(v, Ahi, Alo, N4);
    trans_split_kernel<<<tgrid, 256>>>(wv, Whi, Wlo);
    gemm_mma_kernel<<<ggrid, 256, GEMM_DYN_SMEM>>>(Ahi, Alo, Whi, Wlo, bv, Vf);

    // attention
    dim3 agrid(SEQ / AT_BM, NHEADS, BATCH);      // (16, 16, 4)
    attention_kernel<<<agrid, 128>>>(Qf, Kf, Vf, Of);

    // out = O @ wo + bo
    split_kernel<<<(N4 + 255) / 256, 256>>>(Of, Ahi, Alo, N4);
    trans_split_kernel<<<tgrid, 256>>>(wo, Whi, Wlo);
    gemm_mma_kernel<<<ggrid, 256, GEMM_DYN_SMEM>>>(Ahi, Alo, Whi, Wlo, bo, out);
}

// round 7
// speedup vs baseline: 4.6103x; 3.6799x over previous
#include <cuda_runtime.h>
#include <cuda_bf16.h>
#include <cuda_fp16.h>
#include <cstdint>
#include <math.h>

// Problem constants
#define BATCH   4
#define SEQ     2048
#define DMODEL  1024
#define NHEADS  16
#define DHEAD   64
#define MROWS   (BATCH * SEQ)   // 8192

// -------------------- scratch (device globals; no allocation) --------------------
__device__ __half g_Qh[(size_t)MROWS * DMODEL];
__device__ __half g_Kh[(size_t)MROWS * DMODEL];
__device__ __half g_Vh[(size_t)MROWS * DMODEL];
__device__ __nv_bfloat16 g_Ahi[(size_t)MROWS * DMODEL];
__device__ __nv_bfloat16 g_Alo[(size_t)MROWS * DMODEL];
__device__ __nv_bfloat16 g_Whi[(size_t)DMODEL * DMODEL];
__device__ __nv_bfloat16 g_Wlo[(size_t)DMODEL * DMODEL];

// ==================== PTX helpers (base-sm_103 legal) ====================
__device__ __forceinline__ uint32_t smem_u32(const void* p) {
    uint32_t a;
    asm("{ .reg .u64 t; cvta.to.shared.u64 t, %1; cvt.u32.u64 %0, t; }" : "=r"(a) : "l"(p));
    return a;
}
__device__ __forceinline__ void cpa16(uint32_t s, const void* g) {
    asm volatile("cp.async.cg.shared.global [%0], [%1], 16;" :: "r"(s), "l"(g));
}
__device__ __forceinline__ void cpa_commit() {
    asm volatile("cp.async.commit_group;" ::: "memory");
}
__device__ __forceinline__ void ldsm_x4(uint32_t& r0, uint32_t& r1, uint32_t& r2, uint32_t& r3,
                                        uint32_t addr) {
    asm volatile("ldmatrix.sync.aligned.m8n8.x4.shared.b16 {%0,%1,%2,%3}, [%4];"
                 : "=r"(r0), "=r"(r1), "=r"(r2), "=r"(r3) : "r"(addr));
}
__device__ __forceinline__ void ldsm_x4t(uint32_t& r0, uint32_t& r1, uint32_t& r2, uint32_t& r3,
                                         uint32_t addr) {
    asm volatile("ldmatrix.sync.aligned.m8n8.x4.trans.shared.b16 {%0,%1,%2,%3}, [%4];"
                 : "=r"(r0), "=r"(r1), "=r"(r2), "=r"(r3) : "r"(addr));
}
__device__ __forceinline__ void mma_bf16(float* d, const uint32_t* a, const uint32_t* b) {
    asm volatile(
        "mma.sync.aligned.m16n8k16.row.col.f32.bf16.bf16.f32 "
        "{%0,%1,%2,%3}, {%4,%5,%6,%7}, {%8,%9}, {%0,%1,%2,%3};"
        : "+f"(d[0]), "+f"(d[1]), "+f"(d[2]), "+f"(d[3])
        : "r"(a[0]), "r"(a[1]), "r"(a[2]), "r"(a[3]), "r"(b[0]), "r"(b[1]));
}
__device__ __forceinline__ void mma_f16(float* d, const uint32_t* a, const uint32_t* b) {
    asm volatile(
        "mma.sync.aligned.m16n8k16.row.col.f32.f16.f16.f32 "
        "{%0,%1,%2,%3}, {%4,%5,%6,%7}, {%8,%9}, {%0,%1,%2,%3};"
        : "+f"(d[0]), "+f"(d[1]), "+f"(d[2]), "+f"(d[3])
        : "r"(a[0]), "r"(a[1]), "r"(a[2]), "r"(a[3]), "r"(b[0]), "r"(b[1]));
}
// pack {lo, hi} floats into one f16x2 register (lo -> bits[0:16))
__device__ __forceinline__ uint32_t packh2(float hi, float lo) {
    uint32_t r;
    asm("cvt.rn.f16x2.f32 %0, %1, %2;" : "=r"(r) : "f"(hi), "f"(lo));
    return r;
}

// ==================== pre-pass: fp32 -> bf16 hi/lo split ====================
__global__ __launch_bounds__(256)
void split_kernel(const float* __restrict__ in, __nv_bfloat16* __restrict__ hi,
                  __nv_bfloat16* __restrict__ lo, int n4) {
    int i = blockIdx.x * blockDim.x + threadIdx.x;
    if (i >= n4) return;
    float4 v = ((const float4*)in)[i];
    float vv[4] = {v.x, v.y, v.z, v.w};
    __nv_bfloat16 h[4], l[4];
#pragma unroll
    for (int j = 0; j < 4; j++) {
        h[j] = __float2bfloat16(vv[j]);
        l[j] = __float2bfloat16(vv[j] - __bfloat162float(h[j]));
    }
    ((uint2*)hi)[i] = *(uint2*)h;
    ((uint2*)lo)[i] = *(uint2*)l;
}

// ==================== pre-pass: W[K,N] -> WT[N,K] bf16 hi/lo ====================
__global__ __launch_bounds__(256)
void trans_split_kernel(const float* __restrict__ W, __nv_bfloat16* __restrict__ hi,
                        __nv_bfloat16* __restrict__ lo) {
    __shared__ float tile[32][33];
    const int tx = threadIdx.x & 31, tyo = threadIdx.x >> 5;   // 32x8
    const int x = blockIdx.x * 32 + tx;
    const int y0 = blockIdx.y * 32;
#pragma unroll
    for (int r = tyo; r < 32; r += 8)
        tile[r][tx] = W[(size_t)(y0 + r) * DMODEL + x];
    __syncthreads();
    const int n0 = blockIdx.x * 32;
    const int k  = y0 + tx;
#pragma unroll
    for (int r = tyo; r < 32; r += 8) {
        float v = tile[tx][r];
        __nv_bfloat16 h = __float2bfloat16(v);
        __nv_bfloat16 l = __float2bfloat16(v - __bfloat162float(h));
        hi[(size_t)(n0 + r) * DMODEL + k] = h;
        lo[(size_t)(n0 + r) * DMODEL + k] = l;
    }
}

// ==================== mma.sync GEMM: C = (A @ W + bias) * outscale ============
// CTA 128x128, BK=32, 8 warps. Writes fp16 (Ch) or fp32 (Cf).
#define BM 128
#define BN 128
#define BK 32
#define PADB 80
#define TILE_B (128 * PADB)
#define STAGE_B (4 * TILE_B)
#define GEMM_DYN_SMEM (2 * STAGE_B)
#define NCHUNK (DMODEL / BK)

__global__ __launch_bounds__(256)
void gemm_mma_kernel(const __nv_bfloat16* __restrict__ Ahi, const __nv_bfloat16* __restrict__ Alo,
                     const __nv_bfloat16* __restrict__ Bhi, const __nv_bfloat16* __restrict__ Blo,
                     const float* __restrict__ bias, float outscale,
                     __half* __restrict__ Ch, float* __restrict__ Cf) {
    extern __shared__ char smem[];
    const uint32_t sb = smem_u32(smem);
    const int t = threadIdx.x;
    const int lane = t & 31;
    const int wid  = t >> 5;
    const int wm   = wid & 3;
    const int wn   = wid >> 2;
    const int m0 = blockIdx.y * BM;
    const int n0 = blockIdx.x * BN;

    const uint32_t a_off = (uint32_t)((wm * 32 + (lane & 15)) * PADB + (lane >> 4) * 16);
    const uint32_t b_off = (uint32_t)((wn * 64 + ((lane >> 4) & 1) * 8 + (lane & 7)) * PADB
                                      + ((lane >> 3) & 1) * 16);

    auto load_stage = [&](int c, int s) {
        const uint32_t st = sb + (uint32_t)s * STAGE_B;
        const int k0 = c * BK;
#pragma unroll
        for (int h = 0; h < 2; h++) {
            int idx = t + h * 256;
            int row = idx >> 2, cc = idx & 3;
            uint32_t so = (uint32_t)(row * PADB + cc * 16);
            size_t ga = (size_t)(m0 + row) * DMODEL + k0 + cc * 8;
            size_t gb = (size_t)(n0 + row) * DMODEL + k0 + cc * 8;
            cpa16(st + 0 * TILE_B + so, Ahi + ga);
            cpa16(st + 1 * TILE_B + so, Alo + ga);
            cpa16(st + 2 * TILE_B + so, Bhi + gb);
            cpa16(st + 3 * TILE_B + so, Blo + gb);
        }
        cpa_commit();
    };

    float acc[2][8][4];
#pragma unroll
    for (int i = 0; i < 2; i++)
#pragma unroll
        for (int j = 0; j < 8; j++)
#pragma unroll
            for (int r = 0; r < 4; r++) acc[i][j][r] = 0.f;

    load_stage(0, 0);

    for (int c = 0; c < NCHUNK; c++) {
        if (c + 1 < NCHUNK) {
            load_stage(c + 1, (c + 1) & 1);
            asm volatile("cp.async.wait_group 1;" ::: "memory");
        } else {
            asm volatile("cp.async.wait_group 0;" ::: "memory");
        }
        __syncthreads();

        const uint32_t st = sb + (uint32_t)(c & 1) * STAGE_B;
#pragma unroll
        for (int ks = 0; ks < BK; ks += 16) {
            uint32_t aH[2][4], aL[2][4], bH[4][4], bL[4][4];
#pragma unroll
            for (int mt = 0; mt < 2; mt++) {
                uint32_t ad = st + a_off + (uint32_t)(mt * 16 * PADB + ks * 2);
                ldsm_x4(aH[mt][0], aH[mt][1], aH[mt][2], aH[mt][3], ad + 0 * TILE_B);
                ldsm_x4(aL[mt][0], aL[mt][1], aL[mt][2], aL[mt][3], ad + 1 * TILE_B);
            }
#pragma unroll
            for (int jp = 0; jp < 4; jp++) {
                uint32_t bd = st + b_off + (uint32_t)(jp * 16 * PADB + ks * 2);
                ldsm_x4(bH[jp][0], bH[jp][1], bH[jp][2], bH[jp][3], bd + 2 * TILE_B);
                ldsm_x4(bL[jp][0], bL[jp][1], bL[jp][2], bL[jp][3], bd + 3 * TILE_B);
            }
#pragma unroll
            for (int mt = 0; mt < 2; mt++)
#pragma unroll
                for (int jp = 0; jp < 4; jp++) {
                    mma_bf16(acc[mt][jp * 2 + 0], aH[mt], &bH[jp][0]);
                    mma_bf16(acc[mt][jp * 2 + 1], aH[mt], &bH[jp][2]);
                    mma_bf16(acc[mt][jp * 2 + 0], aH[mt], &bL[jp][0]);
                    mma_bf16(acc[mt][jp * 2 + 1], aH[mt], &bL[jp][2]);
                    mma_bf16(acc[mt][jp * 2 + 0], aL[mt], &bH[jp][0]);
                    mma_bf16(acc[mt][jp * 2 + 1], aL[mt], &bH[jp][2]);
                }
        }
        __syncthreads();
    }

    // -------- epilogue --------
    const int gid = lane >> 2, tig = lane & 3;
#pragma unroll
    for (int mt = 0; mt < 2; mt++) {
        const int r0 = m0 + wm * 32 + mt * 16 + gid;
#pragma unroll
        for (int j = 0; j < 8; j++) {
            const int col = n0 + wn * 64 + j * 8 + tig * 2;
            const float bx = bias[col], by = bias[col + 1];
            float v0x = (acc[mt][j][0] + bx) * outscale;
            float v0y = (acc[mt][j][1] + by) * outscale;
            float v1x = (acc[mt][j][2] + bx) * outscale;
            float v1y = (acc[mt][j][3] + by) * outscale;
            if (Ch) {
                *(uint32_t*)&Ch[(size_t)r0 * DMODEL + col]       = packh2(v0y, v0x);
                *(uint32_t*)&Ch[(size_t)(r0 + 8) * DMODEL + col] = packh2(v1y, v1x);
            } else {
                float2 a = {v0x, v0y}, b2 = {v1x, v1y};
                *(float2*)&Cf[(size_t)r0 * DMODEL + col]       = a;
                *(float2*)&Cf[(size_t)(r0 + 8) * DMODEL + col] = b2;
            }
        }
    }
}

// ==================== flash attention 2 (fp16 mma.sync) ====================
// CTA: 64 queries x one (b,h); 4 warps, each warp owns 16 query rows.
// KV tiles 64x64 fp16, double-buffered cp.async. Output: bf16 hi/lo split.
#define FA_BM 64
#define FA_BN 64
#define FA_PADH 72                      // halfs per smem row (144B, conflict-free)
#define FA_TILE_H (FA_BM * FA_PADH)     // 4608 halfs = 9216 B

__global__ __launch_bounds__(128, 3)
void fa_kernel(const __half* __restrict__ Qh, const __half* __restrict__ Kh,
               const __half* __restrict__ Vh,
               __nv_bfloat16* __restrict__ Ohi, __nv_bfloat16* __restrict__ Olo) {
    __shared__ __half sQ[FA_TILE_H];
    __shared__ __half sK[2][FA_TILE_H];
    __shared__ __half sV[2][FA_TILE_H];

    const int t = threadIdx.x, lane = t & 31, w = t >> 5;
    const int h = blockIdx.y, b = blockIdx.z;
    const size_t qrow0 = (size_t)b * SEQ + (size_t)blockIdx.x * FA_BM;
    const size_t krow0 = (size_t)b * SEQ;
    const int hd = h * DHEAD;

    const uint32_t sKu = smem_u32(sK), sVu = smem_u32(sV);

    auto load_kv = [&](int kt, int s) {
#pragma unroll
        for (int i = 0; i < 4; i++) {
            int idx = t + i * 128;
            int r = idx >> 3, c = idx & 7;
            uint32_t so = (uint32_t)(s * (FA_TILE_H * 2) + r * (FA_PADH * 2) + c * 16);
            size_t g = (krow0 + (size_t)kt * FA_BN + r) * DMODEL + hd + c * 8;
            cpa16(sKu + so, Kh + g);
            cpa16(sVu + so, Vh + g);
        }
        cpa_commit();
    };

    // stage Q (plain loads) + prefetch KV tile 0
    load_kv(0, 0);
    for (int i = t; i < FA_BM * 8; i += 128) {
        int r = i >> 3, c = i & 7;
        *(uint4*)&sQ[r * FA_PADH + c * 8] =
            *(const uint4*)&Qh[(qrow0 + r) * DMODEL + hd + c * 8];
    }
    __syncthreads();

    // Q a-frags (cached in regs for the whole kernel)
    uint32_t qa[4][4];
    {
        const uint32_t qb_ = smem_u32(sQ);
        uint32_t rb = qb_ + (uint32_t)((w * 16 + (lane & 15)) * (FA_PADH * 2)
                                       + ((lane >> 4) & 1) * 16);
#pragma unroll
        for (int ks = 0; ks < 4; ks++)
            ldsm_x4(qa[ks][0], qa[ks][1], qa[ks][2], qa[ks][3], rb + ks * 32);
    }

    float oacc[8][4];
#pragma unroll
    for (int j = 0; j < 8; j++)
#pragma unroll
        for (int r = 0; r < 4; r++) oacc[j][r] = 0.f;
    float m0 = -1e30f, m1 = -1e30f, l0 = 0.f, l1 = 0.f;

    // per-lane smem offsets (within a tile buffer)
    const uint32_t k_off = (uint32_t)(((lane & 7) + ((lane >> 4) & 1) * 8) * (FA_PADH * 2)
                                      + ((lane >> 3) & 1) * 16);
    const uint32_t v_off = (uint32_t)((lane & 15) * (FA_PADH * 2) + ((lane >> 4) & 1) * 16);

    const int NT = SEQ / FA_BN;   // 32
    for (int kt = 0; kt < NT; kt++) {
        if (kt + 1 < NT) {
            load_kv(kt + 1, (kt + 1) & 1);
            asm volatile("cp.async.wait_group 1;" ::: "memory");
        } else {
            asm volatile("cp.async.wait_group 0;" ::: "memory");
        }
        __syncthreads();

        const uint32_t kb_ = sKu + (uint32_t)(kt & 1) * (FA_TILE_H * 2);
        const uint32_t vb_ = sVu + (uint32_t)(kt & 1) * (FA_TILE_H * 2);

        // ---- S = Q K^T (scale pre-folded into Q) ----
        float sacc[8][4];
#pragma unroll
        for (int j = 0; j < 8; j++)
#pragma unroll
            for (int r = 0; r < 4; r++) sacc[j][r] = 0.f;
#pragma unroll
        for (int ks = 0; ks < 4; ks++)
#pragma unroll
            for (int np = 0; np < 4; np++) {
                uint32_t kb[4];
                ldsm_x4(kb[0], kb[1], kb[2], kb[3],
                        kb_ + k_off + (uint32_t)(np * 16 * (FA_PADH * 2) + ks * 32));
                mma_f16(sacc[np * 2 + 0], qa[ks], &kb[0]);
                mma_f16(sacc[np * 2 + 1], qa[ks], &kb[2]);
            }

        // ---- online softmax (rows: r0 = lane>>2, r1 = r0+8) ----
        float mx0 = -1e30f, mx1 = -1e30f;
#pragma unroll
        for (int j = 0; j < 8; j++) {
            mx0 = fmaxf(mx0, fmaxf(sacc[j][0], sacc[j][1]));
            mx1 = fmaxf(mx1, fmaxf(sacc[j][2], sacc[j][3]));
        }
        mx0 = fmaxf(mx0, __shfl_xor_sync(0xFFFFFFFFu, mx0, 1));
        mx0 = fmaxf(mx0, __shfl_xor_sync(0xFFFFFFFFu, mx0, 2));
        mx1 = fmaxf(mx1, __shfl_xor_sync(0xFFFFFFFFu, mx1, 1));
        mx1 = fmaxf(mx1, __shfl_xor_sync(0xFFFFFFFFu, mx1, 2));
        float mn0 = fmaxf(m0, mx0), mn1 = fmaxf(m1, mx1);
        float c0 = __expf(m0 - mn0), c1 = __expf(m1 - mn1);
        float rs0 = 0.f, rs1 = 0.f;
#pragma unroll
        for (int j = 0; j < 8; j++) {
            sacc[j][0] = __expf(sacc[j][0] - mn0);
            sacc[j][1] = __expf(sacc[j][1] - mn0);
            sacc[j][2] = __expf(sacc[j][2] - mn1);
            sacc[j][3] = __expf(sacc[j][3] - mn1);
            rs0 += sacc[j][0] + sacc[j][1];
            rs1 += sacc[j][2] + sacc[j][3];
        }
        rs0 += __shfl_xor_sync(0xFFFFFFFFu, rs0, 1);
        rs0 += __shfl_xor_sync(0xFFFFFFFFu, rs0, 2);
        rs1 += __shfl_xor_sync(0xFFFFFFFFu, rs1, 1);
        rs1 += __shfl_xor_sync(0xFFFFFFFFu, rs1, 2);
        l0 = l0 * c0 + rs0;
        l1 = l1 * c1 + rs1;
        m0 = mn0; m1 = mn1;
#pragma unroll
        for (int j = 0; j < 8; j++) {
            oacc[j][0] *= c0; oacc[j][1] *= c0;
            oacc[j][2] *= c1; oacc[j][3] *= c1;
        }

        // ---- pack P to fp16 a-frags ----
        uint32_t pa[4][4];
#pragma unroll
        for (int ks = 0; ks < 4; ks++) {
            pa[ks][0] = packh2(sacc[2 * ks][1],     sacc[2 * ks][0]);
            pa[ks][1] = packh2(sacc[2 * ks][3],     sacc[2 * ks][2]);
            pa[ks][2] = packh2(sacc[2 * ks + 1][1], sacc[2 * ks + 1][0]);
            pa[ks][3] = packh2(sacc[2 * ks + 1][3], sacc[2 * ks + 1][2]);
        }

        // ---- O += P V ----
#pragma unroll
        for (int ks = 0; ks < 4; ks++)
#pragma unroll
            for (int np = 0; np < 4; np++) {
                uint32_t vb[4];
                ldsm_x4t(vb[0], vb[1], vb[2], vb[3],
                         vb_ + v_off + (uint32_t)(ks * 16 * (FA_PADH * 2) + np * 32));
                mma_f16(oacc[np * 2 + 0], pa[ks], &vb[0]);
                mma_f16(oacc[np * 2 + 1], pa[ks], &vb[2]);
            }
        __syncthreads();
    }

    // ---- epilogue: normalize, split to bf16 hi/lo, store ----
    const float il0 = 1.f / l0, il1 = 1.f / l1;
    const size_t r0g = qrow0 + w * 16 + (lane >> 2);
    const int colb = hd + (lane & 3) * 2;
#pragma unroll
    for (int j = 0; j < 8; j++) {
        const int col = colb + j * 8;
        float v00 = oacc[j][0] * il0, v01 = oacc[j][1] * il0;
        float v10 = oacc[j][2] * il1, v11 = oacc[j][3] * il1;
        __nv_bfloat16 h00 = __float2bfloat16(v00), h01 = __float2bfloat16(v01);
        __nv_bfloat16 h10 = __float2bfloat16(v10), h11 = __float2bfloat16(v11);
        __nv_bfloat162 hi0; hi0.x = h00; hi0.y = h01;
        __nv_bfloat162 hi1; hi1.x = h10; hi1.y = h11;
        __nv_bfloat162 lo0; lo0.x = __float2bfloat16(v00 - __bfloat162float(h00));
                            lo0.y = __float2bfloat16(v01 - __bfloat162float(h01));
        __nv_bfloat162 lo1; lo1.x = __float2bfloat16(v10 - __bfloat162float(h10));
                            lo1.y = __float2bfloat16(v11 - __bfloat162float(h11));
        *(__nv_bfloat162*)&Ohi[r0g * DMODEL + col]       = hi0;
        *(__nv_bfloat162*)&Ohi[(r0g + 8) * DMODEL + col] = hi1;
        *(__nv_bfloat162*)&Olo[r0g * DMODEL + col]       = lo0;
        *(__nv_bfloat162*)&Olo[(r0g + 8) * DMODEL + col] = lo1;
    }
}

// -------------------- launch --------------------
extern "C" void kernel_launch(void* const* d_in, const int* in_sizes, int n_in,
                              void* d_out, int out_size) {
    // metadata order: v, k, q, wq, bq, wk, bk, wv, bv, wo, bo
    const float* v  = (const float*)d_in[0];
    const float* k  = (const float*)d_in[1];
    const float* q  = (const float*)d_in[2];
    const float* wq = (const float*)d_in[3];
    const float* bq = (const float*)d_in[4];
    const float* wk = (const float*)d_in[5];
    const float* bk = (const float*)d_in[6];
    const float* wv = (const float*)d_in[7];
    const float* bv = (const float*)d_in[8];
    const float* wo = (const float*)d_in[9];
    const float* bo = (const float*)d_in[10];
    float* out = (float*)d_out;

    __half* Qh; cudaGetSymbolAddress((void**)&Qh, g_Qh);
    __half* Kh; cudaGetSymbolAddress((void**)&Kh, g_Kh);
    __half* Vh; cudaGetSymbolAddress((void**)&Vh, g_Vh);
    __nv_bfloat16* Ahi; cudaGetSymbolAddress((void**)&Ahi, g_Ahi);
    __nv_bfloat16* Alo; cudaGetSymbolAddress((void**)&Alo, g_Alo);
    __nv_bfloat16* Whi; cudaGetSymbolAddress((void**)&Whi, g_Whi);
    __nv_bfloat16* Wlo; cudaGetSymbolAddress((void**)&Wlo, g_Wlo);

    cudaFuncSetAttribute(gemm_mma_kernel,
                         cudaFuncAttributeMaxDynamicSharedMemorySize, GEMM_DYN_SMEM);

    const int N4 = MROWS * DMODEL / 4;
    const dim3 tgrid(32, 32);
    const dim3 ggrid(DMODEL / BN, MROWS / BM);   // (8, 64)
    const float qscale = 0.125f;                 // 1/sqrt(DHEAD), folded into Q

    // Q = (q @ wq + bq) * scale  -> fp16
    split_kernel<<<(N4 + 255) / 256, 256>>>(q, Ahi, Alo, N4);
    trans_split_kernel<<<tgrid, 256>>>(wq, Whi, Wlo);
    gemm_mma_kernel<<<ggrid, 256, GEMM_DYN_SMEM>>>(Ahi, Alo, Whi, Wlo, bq, qscale, Qh, nullptr);
    // K -> fp16
    split_kernel<<<(N4 + 255) / 256, 256>>>(k, Ahi, Alo, N4);
    trans_split_kernel<<<tgrid, 256>>>(wk, Whi, Wlo);
    gemm_mma_kernel<<<ggrid, 256, GEMM_DYN_SMEM>>>(Ahi, Alo, Whi, Wlo, bk, 1.0f, Kh, nullptr);
    // V -> fp16
    split_kernel<<<(N4 + 255) / 256, 256>>>(v, Ahi, Alo, N4);
    trans_split_kernel<<<tgrid, 256>>>(wv, Whi, Wlo);
    gemm_mma_kernel<<<ggrid, 256, GEMM_DYN_SMEM>>>(Ahi, Alo, Whi, Wlo, bv, 1.0f, Vh, nullptr);

    // attention -> bf16 hi/lo (feeds final GEMM directly)
    dim3 agrid(SEQ / FA_BM, NHEADS, BATCH);      // (32, 16, 4)
    fa_kernel<<<agrid, 128>>>(Qh, Kh, Vh, Ahi, Alo);

    // out = O @ wo + bo  (fp32)
    trans_split_kernel<<<tgrid, 256>>>(wo, Whi, Wlo);
    gemm_mma_kernel<<<ggrid, 256, GEMM_DYN_SMEM>>>(Ahi, Alo, Whi, Wlo, bo, 1.0f, nullptr, out);
}

// round 8
// speedup vs baseline: 6.7713x; 1.4687x over previous
#include <cuda_runtime.h>
#include <cuda_bf16.h>
#include <cuda_fp16.h>
#include <cstdint>
#include <math.h>

// Problem constants
#define BATCH   4
#define SEQ     2048
#define DMODEL  1024
#define NHEADS  16
#define DHEAD   64
#define MROWS   (BATCH * SEQ)   // 8192

// -------------------- scratch (device globals; no allocation) --------------------
__device__ __half g_Qh[(size_t)MROWS * DMODEL];
__device__ __half g_Kh[(size_t)MROWS * DMODEL];
__device__ __half g_Vh[(size_t)MROWS * DMODEL];
__device__ __half g_Af16[(size_t)MROWS * DMODEL];
__device__ __half g_Wf16[(size_t)DMODEL * DMODEL];
__device__ __nv_bfloat16 g_Ahi[(size_t)MROWS * DMODEL];
__device__ __nv_bfloat16 g_Alo[(size_t)MROWS * DMODEL];
__device__ __nv_bfloat16 g_Whi[(size_t)DMODEL * DMODEL];
__device__ __nv_bfloat16 g_Wlo[(size_t)DMODEL * DMODEL];

// ==================== PTX helpers (base-sm_103 legal) ====================
__device__ __forceinline__ uint32_t smem_u32(const void* p) {
    uint32_t a;
    asm("{ .reg .u64 t; cvta.to.shared.u64 t, %1; cvt.u32.u64 %0, t; }" : "=r"(a) : "l"(p));
    return a;
}
__device__ __forceinline__ void cpa16(uint32_t s, const void* g) {
    asm volatile("cp.async.cg.shared.global [%0], [%1], 16;" :: "r"(s), "l"(g));
}
__device__ __forceinline__ void cpa_commit() {
    asm volatile("cp.async.commit_group;" ::: "memory");
}
__device__ __forceinline__ void ldsm_x4(uint32_t& r0, uint32_t& r1, uint32_t& r2, uint32_t& r3,
                                        uint32_t addr) {
    asm volatile("ldmatrix.sync.aligned.m8n8.x4.shared.b16 {%0,%1,%2,%3}, [%4];"
                 : "=r"(r0), "=r"(r1), "=r"(r2), "=r"(r3) : "r"(addr));
}
__device__ __forceinline__ void ldsm_x4t(uint32_t& r0, uint32_t& r1, uint32_t& r2, uint32_t& r3,
                                         uint32_t addr) {
    asm volatile("ldmatrix.sync.aligned.m8n8.x4.trans.shared.b16 {%0,%1,%2,%3}, [%4];"
                 : "=r"(r0), "=r"(r1), "=r"(r2), "=r"(r3) : "r"(addr));
}
__device__ __forceinline__ void mma_bf16(float* d, const uint32_t* a, const uint32_t* b) {
    asm volatile(
        "mma.sync.aligned.m16n8k16.row.col.f32.bf16.bf16.f32 "
        "{%0,%1,%2,%3}, {%4,%5,%6,%7}, {%8,%9}, {%0,%1,%2,%3};"
        : "+f"(d[0]), "+f"(d[1]), "+f"(d[2]), "+f"(d[3])
        : "r"(a[0]), "r"(a[1]), "r"(a[2]), "r"(a[3]), "r"(b[0]), "r"(b[1]));
}
__device__ __forceinline__ void mma_f16(float* d, const uint32_t* a, const uint32_t* b) {
    asm volatile(
        "mma.sync.aligned.m16n8k16.row.col.f32.f16.f16.f32 "
        "{%0,%1,%2,%3}, {%4,%5,%6,%7}, {%8,%9}, {%0,%1,%2,%3};"
        : "+f"(d[0]), "+f"(d[1]), "+f"(d[2]), "+f"(d[3])
        : "r"(a[0]), "r"(a[1]), "r"(a[2]), "r"(a[3]), "r"(b[0]), "r"(b[1]));
}
__device__ __forceinline__ uint32_t packh2(float hi, float lo) {
    uint32_t r;
    asm("cvt.rn.f16x2.f32 %0, %1, %2;" : "=r"(r) : "f"(hi), "f"(lo));
    return r;
}

// ==================== pre-pass: fp32 -> fp16 ====================
__global__ __launch_bounds__(256)
void conv_f16_kernel(const float* __restrict__ in, __half* __restrict__ out, int n4) {
    int i = blockIdx.x * blockDim.x + threadIdx.x;
    if (i >= n4) return;
    float4 v = ((const float4*)in)[i];
    uint2 r;
    r.x = packh2(v.y, v.x);
    r.y = packh2(v.w, v.z);
    ((uint2*)out)[i] = r;
}

// ==================== pre-pass: W[K,N] -> WT[N,K] fp16 ====================
__global__ __launch_bounds__(256)
void trans_f16_kernel(const float* __restrict__ W, __half* __restrict__ out) {
    __shared__ float tile[32][33];
    const int tx = threadIdx.x & 31, tyo = threadIdx.x >> 5;
    const int x = blockIdx.x * 32 + tx;
    const int y0 = blockIdx.y * 32;
#pragma unroll
    for (int r = tyo; r < 32; r += 8)
        tile[r][tx] = W[(size_t)(y0 + r) * DMODEL + x];
    __syncthreads();
    const int n0 = blockIdx.x * 32;
    const int k  = y0 + tx;
#pragma unroll
    for (int r = tyo; r < 32; r += 8)
        out[(size_t)(n0 + r) * DMODEL + k] = __float2half(tile[tx][r]);
}

// ==================== pre-pass: W[K,N] -> WT[N,K] bf16 hi/lo ====================
__global__ __launch_bounds__(256)
void trans_split_kernel(const float* __restrict__ W, __nv_bfloat16* __restrict__ hi,
                        __nv_bfloat16* __restrict__ lo) {
    __shared__ float tile[32][33];
    const int tx = threadIdx.x & 31, tyo = threadIdx.x >> 5;
    const int x = blockIdx.x * 32 + tx;
    const int y0 = blockIdx.y * 32;
#pragma unroll
    for (int r = tyo; r < 32; r += 8)
        tile[r][tx] = W[(size_t)(y0 + r) * DMODEL + x];
    __syncthreads();
    const int n0 = blockIdx.x * 32;
    const int k  = y0 + tx;
#pragma unroll
    for (int r = tyo; r < 32; r += 8) {
        float v = tile[tx][r];
        __nv_bfloat16 h = __float2bfloat16(v);
        __nv_bfloat16 l = __float2bfloat16(v - __bfloat162float(h));
        hi[(size_t)(n0 + r) * DMODEL + k] = h;
        lo[(size_t)(n0 + r) * DMODEL + k] = l;
    }
}

// ==================== single-pass fp16 GEMM: C = (A@W + bias)*scale -> fp16 ====
// CTA 128x128, BK=64, 8 warps (4M x 2N), warp tile 32x64.
// SMEM rows 144B (72 halfs): conflict-free ldsm, rows start at bank 4r mod 32.
#define HBK 64
#define HROWB 144
#define HTILE_B (128 * HROWB)          // 18432
#define HSTAGE_B (2 * HTILE_B)         // A + B
#define HGEMM_DYN (2 * HSTAGE_B)       // 73728
#define HNCHUNK (DMODEL / HBK)         // 16

__global__ __launch_bounds__(256)
void gemm_f16_kernel(const __half* __restrict__ A, const __half* __restrict__ B,
                     const float* __restrict__ bias, float outscale,
                     __half* __restrict__ C) {
    extern __shared__ char smem[];
    const uint32_t sb = smem_u32(smem);
    const int t = threadIdx.x;
    const int lane = t & 31;
    const int wid  = t >> 5;
    const int wm   = wid & 3;
    const int wn   = wid >> 2;
    const int m0 = blockIdx.y * 128;
    const int n0 = blockIdx.x * 128;

    const uint32_t a_off = (uint32_t)((wm * 32 + (lane & 15)) * HROWB + (lane >> 4) * 16);
    const uint32_t b_off = (uint32_t)((wn * 64 + ((lane >> 4) & 1) * 8 + (lane & 7)) * HROWB
                                      + ((lane >> 3) & 1) * 16);

    auto load_stage = [&](int c, int s) {
        const uint32_t st = sb + (uint32_t)s * HSTAGE_B;
        const int k0 = c * HBK;
#pragma unroll
        for (int h = 0; h < 4; h++) {
            int idx = t + h * 256;             // 0..1023
            int row = idx >> 3, cc = idx & 7;
            uint32_t so = (uint32_t)(row * HROWB + cc * 16);
            cpa16(st + so,           A + (size_t)(m0 + row) * DMODEL + k0 + cc * 8);
            cpa16(st + HTILE_B + so, B + (size_t)(n0 + row) * DMODEL + k0 + cc * 8);
        }
        cpa_commit();
    };

    float acc[2][8][4];
#pragma unroll
    for (int i = 0; i < 2; i++)
#pragma unroll
        for (int j = 0; j < 8; j++)
#pragma unroll
            for (int r = 0; r < 4; r++) acc[i][j][r] = 0.f;

    load_stage(0, 0);

    for (int c = 0; c < HNCHUNK; c++) {
        if (c + 1 < HNCHUNK) {
            load_stage(c + 1, (c + 1) & 1);
            asm volatile("cp.async.wait_group 1;" ::: "memory");
        } else {
            asm volatile("cp.async.wait_group 0;" ::: "memory");
        }
        __syncthreads();

        const uint32_t st = sb + (uint32_t)(c & 1) * HSTAGE_B;
#pragma unroll
        for (int ks = 0; ks < 4; ks++) {        // 4 x K16 slabs
            uint32_t af[2][4], bf[4][4];
#pragma unroll
            for (int mt = 0; mt < 2; mt++)
                ldsm_x4(af[mt][0], af[mt][1], af[mt][2], af[mt][3],
                        st + a_off + (uint32_t)(mt * 16 * HROWB + ks * 32));
#pragma unroll
            for (int jp = 0; jp < 4; jp++)
                ldsm_x4(bf[jp][0], bf[jp][1], bf[jp][2], bf[jp][3],
                        st + HTILE_B + b_off + (uint32_t)(jp * 16 * HROWB + ks * 32));
#pragma unroll
            for (int mt = 0; mt < 2; mt++)
#pragma unroll
                for (int jp = 0; jp < 4; jp++) {
                    mma_f16(acc[mt][jp * 2 + 0], af[mt], &bf[jp][0]);
                    mma_f16(acc[mt][jp * 2 + 1], af[mt], &bf[jp][2]);
                }
        }
        __syncthreads();
    }

    const int gid = lane >> 2, tig = lane & 3;
#pragma unroll
    for (int mt = 0; mt < 2; mt++) {
        const int r0 = m0 + wm * 32 + mt * 16 + gid;
#pragma unroll
        for (int j = 0; j < 8; j++) {
            const int col = n0 + wn * 64 + j * 8 + tig * 2;
            const float bx = bias[col], by = bias[col + 1];
            *(uint32_t*)&C[(size_t)r0 * DMODEL + col] =
                packh2((acc[mt][j][1] + by) * outscale, (acc[mt][j][0] + bx) * outscale);
            *(uint32_t*)&C[(size_t)(r0 + 8) * DMODEL + col] =
                packh2((acc[mt][j][3] + by) * outscale, (acc[mt][j][2] + bx) * outscale);
        }
    }
}

// ==================== 3-pass bf16 GEMM (final projection, fp32 out) ============
#define BM 128
#define BN 128
#define BK 32
#define PADB 80
#define TILE_B (128 * PADB)
#define STAGE_B (4 * TILE_B)
#define GEMM_DYN_SMEM (2 * STAGE_B)
#define NCHUNK (DMODEL / BK)

__global__ __launch_bounds__(256)
void gemm_mma_kernel(const __nv_bfloat16* __restrict__ Ahi, const __nv_bfloat16* __restrict__ Alo,
                     const __nv_bfloat16* __restrict__ Bhi, const __nv_bfloat16* __restrict__ Blo,
                     const float* __restrict__ bias, float* __restrict__ Cf) {
    extern __shared__ char smem[];
    const uint32_t sb = smem_u32(smem);
    const int t = threadIdx.x;
    const int lane = t & 31;
    const int wid  = t >> 5;
    const int wm   = wid & 3;
    const int wn   = wid >> 2;
    const int m0 = blockIdx.y * BM;
    const int n0 = blockIdx.x * BN;

    const uint32_t a_off = (uint32_t)((wm * 32 + (lane & 15)) * PADB + (lane >> 4) * 16);
    const uint32_t b_off = (uint32_t)((wn * 64 + ((lane >> 4) & 1) * 8 + (lane & 7)) * PADB
                                      + ((lane >> 3) & 1) * 16);

    auto load_stage = [&](int c, int s) {
        const uint32_t st = sb + (uint32_t)s * STAGE_B;
        const int k0 = c * BK;
#pragma unroll
        for (int h = 0; h < 2; h++) {
            int idx = t + h * 256;
            int row = idx >> 2, cc = idx & 3;
            uint32_t so = (uint32_t)(row * PADB + cc * 16);
            size_t ga = (size_t)(m0 + row) * DMODEL + k0 + cc * 8;
            size_t gb = (size_t)(n0 + row) * DMODEL + k0 + cc * 8;
            cpa16(st + 0 * TILE_B + so, Ahi + ga);
            cpa16(st + 1 * TILE_B + so, Alo + ga);
            cpa16(st + 2 * TILE_B + so, Bhi + gb);
            cpa16(st + 3 * TILE_B + so, Blo + gb);
        }
        cpa_commit();
    };

    float acc[2][8][4];
#pragma unroll
    for (int i = 0; i < 2; i++)
#pragma unroll
        for (int j = 0; j < 8; j++)
#pragma unroll
            for (int r = 0; r < 4; r++) acc[i][j][r] = 0.f;

    load_stage(0, 0);

    for (int c = 0; c < NCHUNK; c++) {
        if (c + 1 < NCHUNK) {
            load_stage(c + 1, (c + 1) & 1);
            asm volatile("cp.async.wait_group 1;" ::: "memory");
        } else {
            asm volatile("cp.async.wait_group 0;" ::: "memory");
        }
        __syncthreads();

        const uint32_t st = sb + (uint32_t)(c & 1) * STAGE_B;
#pragma unroll
        for (int ks = 0; ks < BK; ks += 16) {
            uint32_t aH[2][4], aL[2][4], bH[4][4], bL[4][4];
#pragma unroll
            for (int mt = 0; mt < 2; mt++) {
                uint32_t ad = st + a_off + (uint32_t)(mt * 16 * PADB + ks * 2);
                ldsm_x4(aH[mt][0], aH[mt][1], aH[mt][2], aH[mt][3], ad + 0 * TILE_B);
                ldsm_x4(aL[mt][0], aL[mt][1], aL[mt][2], aL[mt][3], ad + 1 * TILE_B);
            }
#pragma unroll
            for (int jp = 0; jp < 4; jp++) {
                uint32_t bd = st + b_off + (uint32_t)(jp * 16 * PADB + ks * 2);
                ldsm_x4(bH[jp][0], bH[jp][1], bH[jp][2], bH[jp][3], bd + 2 * TILE_B);
                ldsm_x4(bL[jp][0], bL[jp][1], bL[jp][2], bL[jp][3], bd + 3 * TILE_B);
            }
#pragma unroll
            for (int mt = 0; mt < 2; mt++)
#pragma unroll
                for (int jp = 0; jp < 4; jp++) {
                    mma_bf16(acc[mt][jp * 2 + 0], aH[mt], &bH[jp][0]);
                    mma_bf16(acc[mt][jp * 2 + 1], aH[mt], &bH[jp][2]);
                    mma_bf16(acc[mt][jp * 2 + 0], aH[mt], &bL[jp][0]);
                    mma_bf16(acc[mt][jp * 2 + 1], aH[mt], &bL[jp][2]);
                    mma_bf16(acc[mt][jp * 2 + 0], aL[mt], &bH[jp][0]);
                    mma_bf16(acc[mt][jp * 2 + 1], aL[mt], &bH[jp][2]);
                }
        }
        __syncthreads();
    }

    const int gid = lane >> 2, tig = lane & 3;
#pragma unroll
    for (int mt = 0; mt < 2; mt++) {
        const int r0 = m0 + wm * 32 + mt * 16 + gid;
#pragma unroll
        for (int j = 0; j < 8; j++) {
            const int col = n0 + wn * 64 + j * 8 + tig * 2;
            const float bx = bias[col], by = bias[col + 1];
            float2 a = {acc[mt][j][0] + bx, acc[mt][j][1] + by};
            float2 b2 = {acc[mt][j][2] + bx, acc[mt][j][3] + by};
            *(float2*)&Cf[(size_t)r0 * DMODEL + col]       = a;
            *(float2*)&Cf[(size_t)(r0 + 8) * DMODEL + col] = b2;
        }
    }
}

// ==================== flash attention 2 (fp16 mma.sync) ====================
#define FA_BM 64
#define FA_BN 64
#define FA_PADH 72
#define FA_TILE_H (FA_BM * FA_PADH)

__global__ __launch_bounds__(128, 3)
void fa_kernel(const __half* __restrict__ Qh, const __half* __restrict__ Kh,
               const __half* __restrict__ Vh,
               __nv_bfloat16* __restrict__ Ohi, __nv_bfloat16* __restrict__ Olo) {
    __shared__ __half sQ[FA_TILE_H];
    __shared__ __half sK[2][FA_TILE_H];
    __shared__ __half sV[2][FA_TILE_H];

    const int t = threadIdx.x, lane = t & 31, w = t >> 5;
    const int h = blockIdx.y, b = blockIdx.z;
    const size_t qrow0 = (size_t)b * SEQ + (size_t)blockIdx.x * FA_BM;
    const size_t krow0 = (size_t)b * SEQ;
    const int hd = h * DHEAD;

    const uint32_t sKu = smem_u32(sK), sVu = smem_u32(sV);

    auto load_kv = [&](int kt, int s) {
#pragma unroll
        for (int i = 0; i < 4; i++) {
            int idx = t + i * 128;
            int r = idx >> 3, c = idx & 7;
            uint32_t so = (uint32_t)(s * (FA_TILE_H * 2) + r * (FA_PADH * 2) + c * 16);
            size_t g = (krow0 + (size_t)kt * FA_BN + r) * DMODEL + hd + c * 8;
            cpa16(sKu + so, Kh + g);
            cpa16(sVu + so, Vh + g);
        }
        cpa_commit();
    };

    load_kv(0, 0);
    for (int i = t; i < FA_BM * 8; i += 128) {
        int r = i >> 3, c = i & 7;
        *(uint4*)&sQ[r * FA_PADH + c * 8] =
            *(const uint4*)&Qh[(qrow0 + r) * DMODEL + hd + c * 8];
    }
    __syncthreads();

    uint32_t qa[4][4];
    {
        const uint32_t qb_ = smem_u32(sQ);
        uint32_t rb = qb_ + (uint32_t)((w * 16 + (lane & 15)) * (FA_PADH * 2)
                                       + ((lane >> 4) & 1) * 16);
#pragma unroll
        for (int ks = 0; ks < 4; ks++)
            ldsm_x4(qa[ks][0], qa[ks][1], qa[ks][2], qa[ks][3], rb + ks * 32);
    }

    float oacc[8][4];
#pragma unroll
    for (int j = 0; j < 8; j++)
#pragma unroll
        for (int r = 0; r < 4; r++) oacc[j][r] = 0.f;
    float m0 = -1e30f, m1 = -1e30f, l0 = 0.f, l1 = 0.f;

    const uint32_t k_off = (uint32_t)(((lane & 7) + ((lane >> 4) & 1) * 8) * (FA_PADH * 2)
                                      + ((lane >> 3) & 1) * 16);
    const uint32_t v_off = (uint32_t)((lane & 15) * (FA_PADH * 2) + ((lane >> 4) & 1) * 16);

    const int NT = SEQ / FA_BN;
    for (int kt = 0; kt < NT; kt++) {
        if (kt + 1 < NT) {
            load_kv(kt + 1, (kt + 1) & 1);
            asm volatile("cp.async.wait_group 1;" ::: "memory");
        } else {
            asm volatile("cp.async.wait_group 0;" ::: "memory");
        }
        __syncthreads();

        const uint32_t kb_ = sKu + (uint32_t)(kt & 1) * (FA_TILE_H * 2);
        const uint32_t vb_ = sVu + (uint32_t)(kt & 1) * (FA_TILE_H * 2);

        float sacc[8][4];
#pragma unroll
        for (int j = 0; j < 8; j++)
#pragma unroll
            for (int r = 0; r < 4; r++) sacc[j][r] = 0.f;
#pragma unroll
        for (int ks = 0; ks < 4; ks++)
#pragma unroll
            for (int np = 0; np < 4; np++) {
                uint32_t kb[4];
                ldsm_x4(kb[0], kb[1], kb[2], kb[3],
                        kb_ + k_off + (uint32_t)(np * 16 * (FA_PADH * 2) + ks * 32));
                mma_f16(sacc[np * 2 + 0], qa[ks], &kb[0]);
                mma_f16(sacc[np * 2 + 1], qa[ks], &kb[2]);
            }

        float mx0 = -1e30f, mx1 = -1e30f;
#pragma unroll
        for (int j = 0; j < 8; j++) {
            mx0 = fmaxf(mx0, fmaxf(sacc[j][0], sacc[j][1]));
            mx1 = fmaxf(mx1, fmaxf(sacc[j][2], sacc[j][3]));
        }
        mx0 = fmaxf(mx0, __shfl_xor_sync(0xFFFFFFFFu, mx0, 1));
        mx0 = fmaxf(mx0, __shfl_xor_sync(0xFFFFFFFFu, mx0, 2));
        mx1 = fmaxf(mx1, __shfl_xor_sync(0xFFFFFFFFu, mx1, 1));
        mx1 = fmaxf(mx1, __shfl_xor_sync(0xFFFFFFFFu, mx1, 2));
        float mn0 = fmaxf(m0, mx0), mn1 = fmaxf(m1, mx1);
        float c0 = __expf(m0 - mn0), c1 = __expf(m1 - mn1);
        float rs0 = 0.f, rs1 = 0.f;
#pragma unroll
        for (int j = 0; j < 8; j++) {
            sacc[j][0] = __expf(sacc[j][0] - mn0);
            sacc[j][1] = __expf(sacc[j][1] - mn0);
            sacc[j][2] = __expf(sacc[j][2] - mn1);
            sacc[j][3] = __expf(sacc[j][3] - mn1);
            rs0 += sacc[j][0] + sacc[j][1];
            rs1 += sacc[j][2] + sacc[j][3];
        }
        rs0 += __shfl_xor_sync(0xFFFFFFFFu, rs0, 1);
        rs0 += __shfl_xor_sync(0xFFFFFFFFu, rs0, 2);
        rs1 += __shfl_xor_sync(0xFFFFFFFFu, rs1, 1);
        rs1 += __shfl_xor_sync(0xFFFFFFFFu, rs1, 2);
        l0 = l0 * c0 + rs0;
        l1 = l1 * c1 + rs1;
        m0 = mn0; m1 = mn1;
#pragma unroll
        for (int j = 0; j < 8; j++) {
            oacc[j][0] *= c0; oacc[j][1] *= c0;
            oacc[j][2] *= c1; oacc[j][3] *= c1;
        }

        uint32_t pa[4][4];
#pragma unroll
        for (int ks = 0; ks < 4; ks++) {
            pa[ks][0] = packh2(sacc[2 * ks][1],     sacc[2 * ks][0]);
            pa[ks][1] = packh2(sacc[2 * ks][3],     sacc[2 * ks][2]);
            pa[ks][2] = packh2(sacc[2 * ks + 1][1], sacc[2 * ks + 1][0]);
            pa[ks][3] = packh2(sacc[2 * ks + 1][3], sacc[2 * ks + 1][2]);
        }

#pragma unroll
        for (int ks = 0; ks < 4; ks++)
#pragma unroll
            for (int np = 0; np < 4; np++) {
                uint32_t vb[4];
                ldsm_x4t(vb[0], vb[1], vb[2], vb[3],
                         vb_ + v_off + (uint32_t)(ks * 16 * (FA_PADH * 2) + np * 32));
                mma_f16(oacc[np * 2 + 0], pa[ks], &vb[0]);
                mma_f16(oacc[np * 2 + 1], pa[ks], &vb[2]);
            }
        __syncthreads();
    }

    const float il0 = 1.f / l0, il1 = 1.f / l1;
    const size_t r0g = qrow0 + w * 16 + (lane >> 2);
    const int colb = hd + (lane & 3) * 2;
#pragma unroll
    for (int j = 0; j < 8; j++) {
        const int col = colb + j * 8;
        float v00 = oacc[j][0] * il0, v01 = oacc[j][1] * il0;
        float v10 = oacc[j][2] * il1, v11 = oacc[j][3] * il1;
        __nv_bfloat16 h00 = __float2bfloat16(v00), h01 = __float2bfloat16(v01);
        __nv_bfloat16 h10 = __float2bfloat16(v10), h11 = __float2bfloat16(v11);
        __nv_bfloat162 hi0; hi0.x = h00; hi0.y = h01;
        __nv_bfloat162 hi1; hi1.x = h10; hi1.y = h11;
        __nv_bfloat162 lo0; lo0.x = __float2bfloat16(v00 - __bfloat162float(h00));
                            lo0.y = __float2bfloat16(v01 - __bfloat162float(h01));
        __nv_bfloat162 lo1; lo1.x = __float2bfloat16(v10 - __bfloat162float(h10));
                            lo1.y = __float2bfloat16(v11 - __bfloat162float(h11));
        *(__nv_bfloat162*)&Ohi[r0g * DMODEL + col]       = hi0;
        *(__nv_bfloat162*)&Ohi[(r0g + 8) * DMODEL + col] = hi1;
        *(__nv_bfloat162*)&Olo[r0g * DMODEL + col]       = lo0;
        *(__nv_bfloat162*)&Olo[(r0g + 8) * DMODEL + col] = lo1;
    }
}

// -------------------- launch --------------------
extern "C" void kernel_launch(void* const* d_in, const int* in_sizes, int n_in,
                              void* d_out, int out_size) {
    // metadata order: v, k, q, wq, bq, wk, bk, wv, bv, wo, bo
    const float* v  = (const float*)d_in[0];
    const float* k  = (const float*)d_in[1];
    const float* q  = (const float*)d_in[2];
    const float* wq = (const float*)d_in[3];
    const float* bq = (const float*)d_in[4];
    const float* wk = (const float*)d_in[5];
    const float* bk = (const float*)d_in[6];
    const float* wv = (const float*)d_in[7];
    const float* bv = (const float*)d_in[8];
    const float* wo = (const float*)d_in[9];
    const float* bo = (const float*)d_in[10];
    float* out = (float*)d_out;

    __half* Qh;  cudaGetSymbolAddress((void**)&Qh, g_Qh);
    __half* Kh;  cudaGetSymbolAddress((void**)&Kh, g_Kh);
    __half* Vh;  cudaGetSymbolAddress((void**)&Vh, g_Vh);
    __half* Af;  cudaGetSymbolAddress((void**)&Af, g_Af16);
    __half* Wf;  cudaGetSymbolAddress((void**)&Wf, g_Wf16);
    __nv_bfloat16* Ahi; cudaGetSymbolAddress((void**)&Ahi, g_Ahi);
    __nv_bfloat16* Alo; cudaGetSymbolAddress((void**)&Alo, g_Alo);
    __nv_bfloat16* Whi; cudaGetSymbolAddress((void**)&Whi, g_Whi);
    __nv_bfloat16* Wlo; cudaGetSymbolAddress((void**)&Wlo, g_Wlo);

    cudaFuncSetAttribute(gemm_mma_kernel,
                         cudaFuncAttributeMaxDynamicSharedMemorySize, GEMM_DYN_SMEM);
    cudaFuncSetAttribute(gemm_f16_kernel,
                         cudaFuncAttributeMaxDynamicSharedMemorySize, HGEMM_DYN);

    const int N4 = MROWS * DMODEL / 4;
    const dim3 tgrid(32, 32);
    const dim3 ggrid(DMODEL / 128, MROWS / 128);   // (8, 64)
    const float qscale = 0.125f;                   // 1/sqrt(DHEAD), folded into Q

    // Q = (q @ wq + bq) * scale -> fp16, single-pass fp16 GEMM
    conv_f16_kernel<<<(N4 + 255) / 256, 256>>>(q, Af, N4);
    trans_f16_kernel<<<tgrid, 256>>>(wq, Wf);
    gemm_f16_kernel<<<ggrid, 256, HGEMM_DYN>>>(Af, Wf, bq, qscale, Qh);
    // K
    conv_f16_kernel<<<(N4 + 255) / 256, 256>>>(k, Af, N4);
    trans_f16_kernel<<<tgrid, 256>>>(wk, Wf);
    gemm_f16_kernel<<<ggrid, 256, HGEMM_DYN>>>(Af, Wf, bk, 1.0f, Kh);
    // V
    conv_f16_kernel<<<(N4 + 255) / 256, 256>>>(v, Af, N4);
    trans_f16_kernel<<<tgrid, 256>>>(wv, Wf);
    gemm_f16_kernel<<<ggrid, 256, HGEMM_DYN>>>(Af, Wf, bv, 1.0f, Vh);

    // attention -> bf16 hi/lo (feeds final GEMM directly)
    dim3 agrid(SEQ / FA_BM, NHEADS, BATCH);        // (32, 16, 4)
    fa_kernel<<<agrid, 128>>>(Qh, Kh, Vh, Ahi, Alo);

    // out = O @ wo + bo  (3-pass bf16, fp32 out)
    trans_split_kernel<<<tgrid, 256>>>(wo, Whi, Wlo);
    gemm_mma_kernel<<<ggrid, 256, GEMM_DYN_SMEM>>>(Ahi, Alo, Whi, Wlo, bo, out);
}

// round 10
// speedup vs baseline: 7.3159x; 1.0804x over previous
#include <cuda_runtime.h>
#include <cuda_bf16.h>
#include <cuda_fp16.h>
#include <cstdint>
#include <math.h>

// Problem constants
#define BATCH   4
#define SEQ     2048
#define DMODEL  1024
#define NHEADS  16
#define DHEAD   64
#define MROWS   (BATCH * SEQ)   // 8192

// -------------------- scratch (device globals; no allocation) --------------------
__device__ __half g_Qh[(size_t)MROWS * DMODEL];
__device__ __half g_Kh[(size_t)MROWS * DMODEL];
__device__ __half g_Vh[(size_t)MROWS * DMODEL];
__device__ __half g_Af16[(size_t)MROWS * DMODEL];
__device__ __half g_Wf16[(size_t)DMODEL * DMODEL];
__device__ __nv_bfloat16 g_Ahi[(size_t)MROWS * DMODEL];
__device__ __nv_bfloat16 g_Alo[(size_t)MROWS * DMODEL];
__device__ __nv_bfloat16 g_Whi[(size_t)DMODEL * DMODEL];
__device__ __nv_bfloat16 g_Wlo[(size_t)DMODEL * DMODEL];

// ==================== PTX helpers (base-sm_103 legal) ====================
__device__ __forceinline__ uint32_t smem_u32(const void* p) {
    uint32_t a;
    asm("{ .reg .u64 t; cvta.to.shared.u64 t, %1; cvt.u32.u64 %0, t; }" : "=r"(a) : "l"(p));
    return a;
}
__device__ __forceinline__ void cpa16(uint32_t s, const void* g) {
    asm volatile("cp.async.cg.shared.global [%0], [%1], 16;" :: "r"(s), "l"(g));
}
__device__ __forceinline__ void cpa_commit() {
    asm volatile("cp.async.commit_group;" ::: "memory");
}
__device__ __forceinline__ void ldsm_x4(uint32_t& r0, uint32_t& r1, uint32_t& r2, uint32_t& r3,
                                        uint32_t addr) {
    asm volatile("ldmatrix.sync.aligned.m8n8.x4.shared.b16 {%0,%1,%2,%3}, [%4];"
                 : "=r"(r0), "=r"(r1), "=r"(r2), "=r"(r3) : "r"(addr));
}
__device__ __forceinline__ void ldsm_x4t(uint32_t& r0, uint32_t& r1, uint32_t& r2, uint32_t& r3,
                                         uint32_t addr) {
    asm volatile("ldmatrix.sync.aligned.m8n8.x4.trans.shared.b16 {%0,%1,%2,%3}, [%4];"
                 : "=r"(r0), "=r"(r1), "=r"(r2), "=r"(r3) : "r"(addr));
}
__device__ __forceinline__ void mma_bf16(float* d, const uint32_t* a, const uint32_t* b) {
    asm volatile(
        "mma.sync.aligned.m16n8k16.row.col.f32.bf16.bf16.f32 "
        "{%0,%1,%2,%3}, {%4,%5,%6,%7}, {%8,%9}, {%0,%1,%2,%3};"
        : "+f"(d[0]), "+f"(d[1]), "+f"(d[2]), "+f"(d[3])
        : "r"(a[0]), "r"(a[1]), "r"(a[2]), "r"(a[3]), "r"(b[0]), "r"(b[1]));
}
__device__ __forceinline__ void mma_f16(float* d, const uint32_t* a, const uint32_t* b) {
    asm volatile(
        "mma.sync.aligned.m16n8k16.row.col.f32.f16.f16.f32 "
        "{%0,%1,%2,%3}, {%4,%5,%6,%7}, {%8,%9}, {%0,%1,%2,%3};"
        : "+f"(d[0]), "+f"(d[1]), "+f"(d[2]), "+f"(d[3])
        : "r"(a[0]), "r"(a[1]), "r"(a[2]), "r"(a[3]), "r"(b[0]), "r"(b[1]));
}
__device__ __forceinline__ uint32_t packh2(float hi, float lo) {
    uint32_t r;
    asm("cvt.rn.f16x2.f32 %0, %1, %2;" : "=r"(r) : "f"(hi), "f"(lo));
    return r;
}

// ==================== pre-pass: fp32 -> fp16 (layout-preserving) ====================
__global__ __launch_bounds__(256)
void conv_f16_kernel(const float* __restrict__ in, __half* __restrict__ out, int n4) {
    int i = blockIdx.x * blockDim.x + threadIdx.x;
    if (i >= n4) return;
    float4 v = ((const float4*)in)[i];
    uint2 r;
    r.x = packh2(v.y, v.x);
    r.y = packh2(v.w, v.z);
    ((uint2*)out)[i] = r;
}

// ==================== pre-pass: fp32 -> bf16 hi/lo (layout-preserving) ==============
__global__ __launch_bounds__(256)
void split_kernel(const float* __restrict__ in, __nv_bfloat16* __restrict__ hi,
                  __nv_bfloat16* __restrict__ lo, int n4) {
    int i = blockIdx.x * blockDim.x + threadIdx.x;
    if (i >= n4) return;
    float4 v = ((const float4*)in)[i];
    float vv[4] = {v.x, v.y, v.z, v.w};
    __nv_bfloat16 h[4], l[4];
#pragma unroll
    for (int j = 0; j < 4; j++) {
        h[j] = __float2bfloat16(vv[j]);
        l[j] = __float2bfloat16(vv[j] - __bfloat162float(h[j]));
    }
    ((uint2*)hi)[i] = *(uint2*)h;
    ((uint2*)lo)[i] = *(uint2*)l;
}

// ==================== single-pass fp16 GEMM: C = (A@W + bias)*scale -> fp16 ====
// CTA 128x128, BK=64, 8 warps (4M x 2N). A K-major (144B rows, non-trans ldsm);
// W consumed natively [K,N] (272B rows, ldsm.trans for B-frags).
#define HBK 64
#define HROWB 144
#define WROWB 272
#define HA_B (128 * HROWB)             // 18432
#define HB_B (HBK * WROWB)             // 17408
#define HSTAGE_B (HA_B + HB_B)         // 35840
#define HGEMM_DYN (2 * HSTAGE_B)       // 71680
#define HNCHUNK (DMODEL / HBK)         // 16

__global__ __launch_bounds__(256)
void gemm_f16_kernel(const __half* __restrict__ A, const __half* __restrict__ W,
                     const float* __restrict__ bias, float outscale,
                     __half* __restrict__ C) {
    extern __shared__ char smem[];
    const uint32_t sb = smem_u32(smem);
    const int t = threadIdx.x;
    const int lane = t & 31;
    const int wid  = t >> 5;
    const int wm   = wid & 3;
    const int wn   = wid >> 2;
    const int m0 = blockIdx.y * 128;
    const int n0 = blockIdx.x * 128;

    const uint32_t a_off = (uint32_t)((wm * 32 + (lane & 15)) * HROWB + (lane >> 4) * 16);
    // trans B-frag base: rows = k (lane&15), +16B col offset for upper lanes, warp n-offset
    const uint32_t b_off = (uint32_t)((lane & 15) * WROWB + ((lane >> 4) & 1) * 16 + wn * 128);

    auto load_stage = [&](int c, int s) {
        const uint32_t st = sb + (uint32_t)s * HSTAGE_B;
        const int k0 = c * HBK;
        // A: 128 rows x 8 x 16B = 1024 chunks
#pragma unroll
        for (int h = 0; h < 4; h++) {
            int idx = t + h * 256;
            int row = idx >> 3, cc = idx & 7;
            cpa16(st + (uint32_t)(row * HROWB + cc * 16),
                  A + (size_t)(m0 + row) * DMODEL + k0 + cc * 8);
        }
        // W: 64 k-rows x 16 x 16B = 1024 chunks
#pragma unroll
        for (int h = 0; h < 4; h++) {
            int idx = t + h * 256;
            int row = idx >> 4, cc = idx & 15;
            cpa16(st + HA_B + (uint32_t)(row * WROWB + cc * 16),
                  W + (size_t)(k0 + row) * DMODEL + n0 + cc * 8);
        }
        cpa_commit();
    };

    float acc[2][8][4];
#pragma unroll
    for (int i = 0; i < 2; i++)
#pragma unroll
        for (int j = 0; j < 8; j++)
#pragma unroll
            for (int r = 0; r < 4; r++) acc[i][j][r] = 0.f;

    load_stage(0, 0);

    for (int c = 0; c < HNCHUNK; c++) {
        if (c + 1 < HNCHUNK) {
            load_stage(c + 1, (c + 1) & 1);
            asm volatile("cp.async.wait_group 1;" ::: "memory");
        } else {
            asm volatile("cp.async.wait_group 0;" ::: "memory");
        }
        __syncthreads();

        const uint32_t st = sb + (uint32_t)(c & 1) * HSTAGE_B;
#pragma unroll
        for (int ks = 0; ks < 4; ks++) {        // 4 x K16 slabs
            uint32_t af[2][4], bf[4][4];
#pragma unroll
            for (int mt = 0; mt < 2; mt++)
                ldsm_x4(af[mt][0], af[mt][1], af[mt][2], af[mt][3],
                        st + a_off + (uint32_t)(mt * 16 * HROWB + ks * 32));
#pragma unroll
            for (int np = 0; np < 4; np++)
                ldsm_x4t(bf[np][0], bf[np][1], bf[np][2], bf[np][3],
                         st + HA_B + b_off + (uint32_t)(ks * 16 * WROWB + np * 32));
#pragma unroll
            for (int mt = 0; mt < 2; mt++)
#pragma unroll
                for (int np = 0; np < 4; np++) {
                    mma_f16(acc[mt][np * 2 + 0], af[mt], &bf[np][0]);
                    mma_f16(acc[mt][np * 2 + 1], af[mt], &bf[np][2]);
                }
        }
        __syncthreads();
    }

    const int gid = lane >> 2, tig = lane & 3;
#pragma unroll
    for (int mt = 0; mt < 2; mt++) {
        const int r0 = m0 + wm * 32 + mt * 16 + gid;
#pragma unroll
        for (int j = 0; j < 8; j++) {
            const int col = n0 + wn * 64 + j * 8 + tig * 2;
            const float bx = bias[col], by = bias[col + 1];
            *(uint32_t*)&C[(size_t)r0 * DMODEL + col] =
                packh2((acc[mt][j][1] + by) * outscale, (acc[mt][j][0] + bx) * outscale);
            *(uint32_t*)&C[(size_t)(r0 + 8) * DMODEL + col] =
                packh2((acc[mt][j][3] + by) * outscale, (acc[mt][j][2] + bx) * outscale);
        }
    }
}

// ==================== 3-pass bf16 GEMM (final projection, fp32 out) ============
// A = attention output (hi/lo, K-major, 80B rows). W consumed natively [K,N]
// as bf16 hi/lo (272B rows, ldsm.trans).
#define BK 32
#define PADB 80
#define MA_B (128 * PADB)              // 10240
#define MB_B (BK * WROWB)              // 8704
#define MSTAGE_B (2 * MA_B + 2 * MB_B) // 37888
#define MOFF_ALO MA_B
#define MOFF_BHI (2 * MA_B)
#define MOFF_BLO (2 * MA_B + MB_B)
#define GEMM_DYN_SMEM (2 * MSTAGE_B)   // 75776
#define NCHUNK (DMODEL / BK)

__global__ __launch_bounds__(256)
void gemm_mma_kernel(const __nv_bfloat16* __restrict__ Ahi, const __nv_bfloat16* __restrict__ Alo,
                     const __nv_bfloat16* __restrict__ Whi, const __nv_bfloat16* __restrict__ Wlo,
                     const float* __restrict__ bias, float* __restrict__ Cf) {
    extern __shared__ char smem[];
    const uint32_t sb = smem_u32(smem);
    const int t = threadIdx.x;
    const int lane = t & 31;
    const int wid  = t >> 5;
    const int wm   = wid & 3;
    const int wn   = wid >> 2;
    const int m0 = blockIdx.y * 128;
    const int n0 = blockIdx.x * 128;

    const uint32_t a_off = (uint32_t)((wm * 32 + (lane & 15)) * PADB + (lane >> 4) * 16);
    const uint32_t b_off = (uint32_t)((lane & 15) * WROWB + ((lane >> 4) & 1) * 16 + wn * 128);

    auto load_stage = [&](int c, int s) {
        const uint32_t st = sb + (uint32_t)s * MSTAGE_B;
        const int k0 = c * BK;
        // A arrays: 128 rows x 4 x 16B = 512 chunks each
#pragma unroll
        for (int h = 0; h < 2; h++) {
            int idx = t + h * 256;
            int row = idx >> 2, cc = idx & 3;
            uint32_t so = (uint32_t)(row * PADB + cc * 16);
            size_t ga = (size_t)(m0 + row) * DMODEL + k0 + cc * 8;
            cpa16(st + so,            Ahi + ga);
            cpa16(st + MOFF_ALO + so, Alo + ga);
        }
        // W arrays: 32 k-rows x 16 x 16B = 512 chunks each
#pragma unroll
        for (int h = 0; h < 2; h++) {
            int idx = t + h * 256;
            int row = idx >> 4, cc = idx & 15;
            uint32_t so = (uint32_t)(row * WROWB + cc * 16);
            size_t gb = (size_t)(k0 + row) * DMODEL + n0 + cc * 8;
            cpa16(st + MOFF_BHI + so, Whi + gb);
            cpa16(st + MOFF_BLO + so, Wlo + gb);
        }
        cpa_commit();
    };

    float acc[2][8][4];
#pragma unroll
    for (int i = 0; i < 2; i++)
#pragma unroll
        for (int j = 0; j < 8; j++)
#pragma unroll
            for (int r = 0; r < 4; r++) acc[i][j][r] = 0.f;

    load_stage(0, 0);

    for (int c = 0; c < NCHUNK; c++) {
        if (c + 1 < NCHUNK) {
            load_stage(c + 1, (c + 1) & 1);
            asm volatile("cp.async.wait_group 1;" ::: "memory");
        } else {
            asm volatile("cp.async.wait_group 0;" ::: "memory");
        }
        __syncthreads();

        const uint32_t st = sb + (uint32_t)(c & 1) * MSTAGE_B;
#pragma unroll
        for (int ks = 0; ks < 2; ks++) {        // 2 x K16 slabs
            uint32_t aH[2][4], aL[2][4], bH[4][4], bL[4][4];
#pragma unroll
            for (int mt = 0; mt < 2; mt++) {
                uint32_t ad = st + a_off + (uint32_t)(mt * 16 * PADB + ks * 32);
                ldsm_x4(aH[mt][0], aH[mt][1], aH[mt][2], aH[mt][3], ad);
                ldsm_x4(aL[mt][0], aL[mt][1], aL[mt][2], aL[mt][3], ad + MOFF_ALO);
            }
#pragma unroll
            for (int np = 0; np < 4; np++) {
                uint32_t bd = st + b_off + (uint32_t)(ks * 16 * WROWB + np * 32);
                ldsm_x4t(bH[np][0], bH[np][1], bH[np][2], bH[np][3], bd + MOFF_BHI);
                ldsm_x4t(bL[np][0], bL[np][1], bL[np][2], bL[np][3], bd + MOFF_BLO);
            }
#pragma unroll
            for (int mt = 0; mt < 2; mt++)
#pragma unroll
                for (int np = 0; np < 4; np++) {
                    mma_bf16(acc[mt][np * 2 + 0], aH[mt], &bH[np][0]);
                    mma_bf16(acc[mt][np * 2 + 1], aH[mt], &bH[np][2]);
                    mma_bf16(acc[mt][np * 2 + 0], aH[mt], &bL[np][0]);
                    mma_bf16(acc[mt][np * 2 + 1], aH[mt], &bL[np][2]);
                    mma_bf16(acc[mt][np * 2 + 0], aL[mt], &bH[np][0]);
                    mma_bf16(acc[mt][np * 2 + 1], aL[mt], &bH[np][2]);
                }
        }
        __syncthreads();
    }

    const int gid = lane >> 2, tig = lane & 3;
#pragma unroll
    for (int mt = 0; mt < 2; mt++) {
        const int r0 = m0 + wm * 32 + mt * 16 + gid;
#pragma unroll
        for (int j = 0; j < 8; j++) {
            const int col = n0 + wn * 64 + j * 8 + tig * 2;
            const float bx = bias[col], by = bias[col + 1];
            float2 a = {acc[mt][j][0] + bx, acc[mt][j][1] + by};
            float2 b2 = {acc[mt][j][2] + bx, acc[mt][j][3] + by};
            *(float2*)&Cf[(size_t)r0 * DMODEL + col]       = a;
            *(float2*)&Cf[(size_t)(r0 + 8) * DMODEL + col] = b2;
        }
    }
}

// ==================== flash attention 2 (fp16 mma.sync, BM=128) ====================
// CTA: 128 queries, 4 warps; warp owns 32 q-rows = 2 m16 tiles (sequential).
// KV tiles 64x64 fp16 double-buffered. Halves K/V L2 traffic vs BM=64.
#define FA_BM 128
#define FA_BN 64
#define FA_PADH 72
#define FA_ROWB (FA_PADH * 2)          // 144
#define FA_KV_B (FA_BN * FA_ROWB)      // 9216
#define FA_Q_B  (FA_BM * FA_ROWB)      // 18432
#define FA_DYN  (FA_Q_B + 4 * FA_KV_B) // 55296

__global__ __launch_bounds__(128, 2)
void fa_kernel(const __half* __restrict__ Qh, const __half* __restrict__ Kh,
               const __half* __restrict__ Vh,
               __nv_bfloat16* __restrict__ Ohi, __nv_bfloat16* __restrict__ Olo) {
    extern __shared__ char fsm[];
    const uint32_t sQu = smem_u32(fsm);
    const uint32_t sKu = sQu + FA_Q_B;
    const uint32_t sVu = sKu + 2 * FA_KV_B;
    __half* sQ = (__half*)fsm;

    const int t = threadIdx.x, lane = t & 31, w = t >> 5;
    const int h = blockIdx.y, b = blockIdx.z;
    const size_t qrow0 = (size_t)b * SEQ + (size_t)blockIdx.x * FA_BM;
    const size_t krow0 = (size_t)b * SEQ;
    const int hd = h * DHEAD;

    auto load_kv = [&](int kt, int s) {
#pragma unroll
        for (int i = 0; i < 4; i++) {
            int idx = t + i * 128;
            int r = idx >> 3, c = idx & 7;
            uint32_t so = (uint32_t)(s * FA_KV_B + r * FA_ROWB + c * 16);
            size_t g = (krow0 + (size_t)kt * FA_BN + r) * DMODEL + hd + c * 8;
            cpa16(sKu + so, Kh + g);
            cpa16(sVu + so, Vh + g);
        }
        cpa_commit();
    };

    load_kv(0, 0);
    for (int i = t; i < FA_BM * 8; i += 128) {
        int r = i >> 3, c = i & 7;
        *(uint4*)&sQ[r * FA_PADH + c * 8] =
            *(const uint4*)&Qh[(qrow0 + r) * DMODEL + hd + c * 8];
    }
    __syncthreads();

    // Q a-frags: 2 m-tiles x 4 K16 slabs
    uint32_t qa[2][4][4];
#pragma unroll
    for (int mt = 0; mt < 2; mt++) {
        uint32_t rb = sQu + (uint32_t)((w * 32 + mt * 16 + (lane & 15)) * FA_ROWB
                                       + ((lane >> 4) & 1) * 16);
#pragma unroll
        for (int ks = 0; ks < 4; ks++)
            ldsm_x4(qa[mt][ks][0], qa[mt][ks][1], qa[mt][ks][2], qa[mt][ks][3],
                    rb + ks * 32);
    }

    float oacc[2][8][4];
#pragma unroll
    for (int mt = 0; mt < 2; mt++)
#pragma unroll
        for (int j = 0; j < 8; j++)
#pragma unroll
            for (int r = 0; r < 4; r++) oacc[mt][j][r] = 0.f;
    float mrow[2][2] = {{-1e30f, -1e30f}, {-1e30f, -1e30f}};
    float lrow[2][2] = {{0.f, 0.f}, {0.f, 0.f}};

    const uint32_t k_off = (uint32_t)(((lane & 7) + ((lane >> 4) & 1) * 8) * FA_ROWB
                                      + ((lane >> 3) & 1) * 16);
    const uint32_t v_off = (uint32_t)((lane & 15) * FA_ROWB + ((lane >> 4) & 1) * 16);

    const int NT = SEQ / FA_BN;   // 32
    for (int kt = 0; kt < NT; kt++) {
        if (kt + 1 < NT) {
            load_kv(kt + 1, (kt + 1) & 1);
            asm volatile("cp.async.wait_group 1;" ::: "memory");
        } else {
            asm volatile("cp.async.wait_group 0;" ::: "memory");
        }
        __syncthreads();

        const uint32_t kb_ = sKu + (uint32_t)(kt & 1) * FA_KV_B;
        const uint32_t vb_ = sVu + (uint32_t)(kt & 1) * FA_KV_B;

#pragma unroll
        for (int mt = 0; mt < 2; mt++) {
            // ---- S = Q K^T ----
            float sacc[8][4];
#pragma unroll
            for (int j = 0; j < 8; j++)
#pragma unroll
                for (int r = 0; r < 4; r++) sacc[j][r] = 0.f;
#pragma unroll
            for (int ks = 0; ks < 4; ks++)
#pragma unroll
                for (int np = 0; np < 4; np++) {
                    uint32_t kb[4];
                    ldsm_x4(kb[0], kb[1], kb[2], kb[3],
                            kb_ + k_off + (uint32_t)(np * 16 * FA_ROWB + ks * 32));
                    mma_f16(sacc[np * 2 + 0], qa[mt][ks], &kb[0]);
                    mma_f16(sacc[np * 2 + 1], qa[mt][ks], &kb[2]);
                }

            // ---- online softmax ----
            float mx0 = -1e30f, mx1 = -1e30f;
#pragma unroll
            for (int j = 0; j < 8; j++) {
                mx0 = fmaxf(mx0, fmaxf(sacc[j][0], sacc[j][1]));
                mx1 = fmaxf(mx1, fmaxf(sacc[j][2], sacc[j][3]));
            }
            mx0 = fmaxf(mx0, __shfl_xor_sync(0xFFFFFFFFu, mx0, 1));
            mx0 = fmaxf(mx0, __shfl_xor_sync(0xFFFFFFFFu, mx0, 2));
            mx1 = fmaxf(mx1, __shfl_xor_sync(0xFFFFFFFFu, mx1, 1));
            mx1 = fmaxf(mx1, __shfl_xor_sync(0xFFFFFFFFu, mx1, 2));
            float mn0 = fmaxf(mrow[mt][0], mx0), mn1 = fmaxf(mrow[mt][1], mx1);
            float c0 = __expf(mrow[mt][0] - mn0), c1 = __expf(mrow[mt][1] - mn1);
            float rs0 = 0.f, rs1 = 0.f;
#pragma unroll
            for (int j = 0; j < 8; j++) {
                sacc[j][0] = __expf(sacc[j][0] - mn0);
                sacc[j][1] = __expf(sacc[j][1] - mn0);
                sacc[j][2] = __expf(sacc[j][2] - mn1);
                sacc[j][3] = __expf(sacc[j][3] - mn1);
                rs0 += sacc[j][0] + sacc[j][1];
                rs1 += sacc[j][2] + sacc[j][3];
            }
            rs0 += __shfl_xor_sync(0xFFFFFFFFu, rs0, 1);
            rs0 += __shfl_xor_sync(0xFFFFFFFFu, rs0, 2);
            rs1 += __shfl_xor_sync(0xFFFFFFFFu, rs1, 1);
            rs1 += __shfl_xor_sync(0xFFFFFFFFu, rs1, 2);
            lrow[mt][0] = lrow[mt][0] * c0 + rs0;
            lrow[mt][1] = lrow[mt][1] * c1 + rs1;
            mrow[mt][0] = mn0; mrow[mt][1] = mn1;
#pragma unroll
            for (int j = 0; j < 8; j++) {
                oacc[mt][j][0] *= c0; oacc[mt][j][1] *= c0;
                oacc[mt][j][2] *= c1; oacc[mt][j][3] *= c1;
            }

            // ---- pack P ----
            uint32_t pa[4][4];
#pragma unroll
            for (int ks = 0; ks < 4; ks++) {
                pa[ks][0] = packh2(sacc[2 * ks][1],     sacc[2 * ks][0]);
                pa[ks][1] = packh2(sacc[2 * ks][3],     sacc[2 * ks][2]);
                pa[ks][2] = packh2(sacc[2 * ks + 1][1], sacc[2 * ks + 1][0]);
                pa[ks][3] = packh2(sacc[2 * ks + 1][3], sacc[2 * ks + 1][2]);
            }

            // ---- O += P V ----
#pragma unroll
            for (int ks = 0; ks < 4; ks++)
#pragma unroll
                for (int np = 0; np < 4; np++) {
                    uint32_t vb[4];
                    ldsm_x4t(vb[0], vb[1], vb[2], vb[3],
                             vb_ + v_off + (uint32_t)(ks * 16 * FA_ROWB + np * 32));
                    mma_f16(oacc[mt][np * 2 + 0], pa[ks], &vb[0]);
                    mma_f16(oacc[mt][np * 2 + 1], pa[ks], &vb[2]);
                }
        }
        __syncthreads();
    }

    // ---- epilogue: normalize, split to bf16 hi/lo, store ----
#pragma unroll
    for (int mt = 0; mt < 2; mt++) {
        const float il0 = 1.f / lrow[mt][0], il1 = 1.f / lrow[mt][1];
        const size_t r0g = qrow0 + w * 32 + mt * 16 + (lane >> 2);
        const int colb = hd + (lane & 3) * 2;
#pragma unroll
        for (int j = 0; j < 8; j++) {
            const int col = colb + j * 8;
            float v00 = oacc[mt][j][0] * il0, v01 = oacc[mt][j][1] * il0;
            float v10 = oacc[mt][j][2] * il1, v11 = oacc[mt][j][3] * il1;
            __nv_bfloat16 h00 = __float2bfloat16(v00), h01 = __float2bfloat16(v01);
            __nv_bfloat16 h10 = __float2bfloat16(v10), h11 = __float2bfloat16(v11);
            __nv_bfloat162 hi0; hi0.x = h00; hi0.y = h01;
            __nv_bfloat162 hi1; hi1.x = h10; hi1.y = h11;
            __nv_bfloat162 lo0; lo0.x = __float2bfloat16(v00 - __bfloat162float(h00));
                                lo0.y = __float2bfloat16(v01 - __bfloat162float(h01));
            __nv_bfloat162 lo1; lo1.x = __float2bfloat16(v10 - __bfloat162float(h10));
                                lo1.y = __float2bfloat16(v11 - __bfloat162float(h11));
            *(__nv_bfloat162*)&Ohi[r0g * DMODEL + col]       = hi0;
            *(__nv_bfloat162*)&Ohi[(r0g + 8) * DMODEL + col] = hi1;
            *(__nv_bfloat162*)&Olo[r0g * DMODEL + col]       = lo0;
            *(__nv_bfloat162*)&Olo[(r0g + 8) * DMODEL + col] = lo1;
        }
    }
}

// -------------------- launch --------------------
extern "C" void kernel_launch(void* const* d_in, const int* in_sizes, int n_in,
                              void* d_out, int out_size) {
    // metadata order: v, k, q, wq, bq, wk, bk, wv, bv, wo, bo
    const float* v  = (const float*)d_in[0];
    const float* k  = (const float*)d_in[1];
    const float* q  = (const float*)d_in[2];
    const float* wq = (const float*)d_in[3];
    const float* bq = (const float*)d_in[4];
    const float* wk = (const float*)d_in[5];
    const float* bk = (const float*)d_in[6];
    const float* wv = (const float*)d_in[7];
    const float* bv = (const float*)d_in[8];
    const float* wo = (const float*)d_in[9];
    const float* bo = (const float*)d_in[10];
    float* out = (float*)d_out;

    __half* Qh;  cudaGetSymbolAddress((void**)&Qh, g_Qh);
    __half* Kh;  cudaGetSymbolAddress((void**)&Kh, g_Kh);
    __half* Vh;  cudaGetSymbolAddress((void**)&Vh, g_Vh);
    __half* Af;  cudaGetSymbolAddress((void**)&Af, g_Af16);
    __half* Wf;  cudaGetSymbolAddress((void**)&Wf, g_Wf16);
    __nv_bfloat16* Ahi; cudaGetSymbolAddress((void**)&Ahi, g_Ahi);
    __nv_bfloat16* Alo; cudaGetSymbolAddress((void**)&Alo, g_Alo);
    __nv_bfloat16* Whi; cudaGetSymbolAddress((void**)&Whi, g_Whi);
    __nv_bfloat16* Wlo; cudaGetSymbolAddress((void**)&Wlo, g_Wlo);

    cudaFuncSetAttribute(gemm_mma_kernel,
                         cudaFuncAttributeMaxDynamicSharedMemorySize, GEMM_DYN_SMEM);
    cudaFuncSetAttribute(gemm_f16_kernel,
                         cudaFuncAttributeMaxDynamicSharedMemorySize, HGEMM_DYN);
    cudaFuncSetAttribute(fa_kernel,
                         cudaFuncAttributeMaxDynamicSharedMemorySize, FA_DYN);

    const int N4 = MROWS * DMODEL / 4;     // activation float4s
    const int W4 = DMODEL * DMODEL / 4;    // weight float4s
    const dim3 ggrid(DMODEL / 128, MROWS / 128);   // (8, 64)
    const float qscale = 0.125f;                   // 1/sqrt(DHEAD), folded into Q

    // Q = (q @ wq + bq) * scale -> fp16
    conv_f16_kernel<<<(N4 + 255) / 256, 256>>>(q, Af, N4);
    conv_f16_kernel<<<(W4 + 255) / 256, 256>>>(wq, Wf, W4);
    gemm_f16_kernel<<<ggrid, 256, HGEMM_DYN>>>(Af, Wf, bq, qscale, Qh);
    // K
    conv_f16_kernel<<<(N4 + 255) / 256, 256>>>(k, Af, N4);
    conv_f16_kernel<<<(W4 + 255) / 256, 256>>>(wk, Wf, W4);
    gemm_f16_kernel<<<ggrid, 256, HGEMM_DYN>>>(Af, Wf, bk, 1.0f, Kh);
    // V
    conv_f16_kernel<<<(N4 + 255) / 256, 256>>>(v, Af, N4);
    conv_f16_kernel<<<(W4 + 255) / 256, 256>>>(wv, Wf, W4);
    gemm_f16_kernel<<<ggrid, 256, HGEMM_DYN>>>(Af, Wf, bv, 1.0f, Vh);

    // attention -> bf16 hi/lo (feeds final GEMM directly)
    dim3 agrid(SEQ / FA_BM, NHEADS, BATCH);        // (16, 16, 4)
    fa_kernel<<<agrid, 128, FA_DYN>>>(Qh, Kh, Vh, Ahi, Alo);

    // out = O @ wo + bo  (3-pass bf16, fp32 out)
    split_kernel<<<(W4 + 255) / 256, 256>>>(wo, Whi, Wlo, W4);
    gemm_mma_kernel<<<ggrid, 256, GEMM_DYN_SMEM>>>(Ahi, Alo, Whi, Wlo, bo, out);
}

// round 11
// speedup vs baseline: 8.7819x; 1.2004x over previous
#include <cuda_runtime.h>
#include <cuda_fp16.h>
#include <cstdint>
#include <math.h>

// Problem constants
#define BATCH   4
#define SEQ     2048
#define DMODEL  1024
#define NHEADS  16
#define DHEAD   64
#define MROWS   (BATCH * SEQ)   // 8192

// -------------------- scratch (device globals; no allocation) --------------------
__device__ __half g_Qh[(size_t)MROWS * DMODEL];
__device__ __half g_Kh[(size_t)MROWS * DMODEL];
__device__ __half g_Vh[(size_t)MROWS * DMODEL];
__device__ __half g_Af16[(size_t)MROWS * DMODEL];   // activation fp16 / attention output
__device__ __half g_Wf16[(size_t)DMODEL * DMODEL];  // weight fp16 (native [K,N] layout)

// ==================== PTX helpers (base-sm_103 legal) ====================
__device__ __forceinline__ uint32_t smem_u32(const void* p) {
    uint32_t a;
    asm("{ .reg .u64 t; cvta.to.shared.u64 t, %1; cvt.u32.u64 %0, t; }" : "=r"(a) : "l"(p));
    return a;
}
__device__ __forceinline__ void cpa16(uint32_t s, const void* g) {
    asm volatile("cp.async.cg.shared.global [%0], [%1], 16;" :: "r"(s), "l"(g));
}
__device__ __forceinline__ void cpa_commit() {
    asm volatile("cp.async.commit_group;" ::: "memory");
}
__device__ __forceinline__ void ldsm_x4(uint32_t& r0, uint32_t& r1, uint32_t& r2, uint32_t& r3,
                                        uint32_t addr) {
    asm volatile("ldmatrix.sync.aligned.m8n8.x4.shared.b16 {%0,%1,%2,%3}, [%4];"
                 : "=r"(r0), "=r"(r1), "=r"(r2), "=r"(r3) : "r"(addr));
}
__device__ __forceinline__ void ldsm_x4t(uint32_t& r0, uint32_t& r1, uint32_t& r2, uint32_t& r3,
                                         uint32_t addr) {
    asm volatile("ldmatrix.sync.aligned.m8n8.x4.trans.shared.b16 {%0,%1,%2,%3}, [%4];"
                 : "=r"(r0), "=r"(r1), "=r"(r2), "=r"(r3) : "r"(addr));
}
__device__ __forceinline__ void mma_f16(float* d, const uint32_t* a, const uint32_t* b) {
    asm volatile(
        "mma.sync.aligned.m16n8k16.row.col.f32.f16.f16.f32 "
        "{%0,%1,%2,%3}, {%4,%5,%6,%7}, {%8,%9}, {%0,%1,%2,%3};"
        : "+f"(d[0]), "+f"(d[1]), "+f"(d[2]), "+f"(d[3])
        : "r"(a[0]), "r"(a[1]), "r"(a[2]), "r"(a[3]), "r"(b[0]), "r"(b[1]));
}
__device__ __forceinline__ uint32_t packh2(float hi, float lo) {
    uint32_t r;
    asm("cvt.rn.f16x2.f32 %0, %1, %2;" : "=r"(r) : "f"(hi), "f"(lo));
    return r;
}

// ==================== pre-pass: fp32 -> fp16 (layout-preserving) ====================
__global__ __launch_bounds__(256)
void conv_f16_kernel(const float* __restrict__ in, __half* __restrict__ out, int n4) {
    int i = blockIdx.x * blockDim.x + threadIdx.x;
    if (i >= n4) return;
    float4 v = ((const float4*)in)[i];
    uint2 r;
    r.x = packh2(v.y, v.x);
    r.y = packh2(v.w, v.z);
    ((uint2*)out)[i] = r;
}

// ==================== single-pass fp16 GEMM: C = (A@W + bias)*scale ============
// CTA 128x128, BK=64, 8 warps (4M x 2N). A K-major (144B rows, non-trans ldsm);
// W consumed natively [K,N] (272B rows, ldsm.trans for B-frags).
// Output: fp16 (Ch) or fp32 (Cf) - exactly one non-null.
#define HBK 64
#define HROWB 144
#define WROWB 272
#define HA_B (128 * HROWB)             // 18432
#define HB_B (HBK * WROWB)             // 17408
#define HSTAGE_B (HA_B + HB_B)         // 35840
#define HGEMM_DYN (2 * HSTAGE_B)       // 71680
#define HNCHUNK (DMODEL / HBK)         // 16

__global__ __launch_bounds__(256)
void gemm_f16_kernel(const __half* __restrict__ A, const __half* __restrict__ W,
                     const float* __restrict__ bias, float outscale,
                     __half* __restrict__ Ch, float* __restrict__ Cf) {
    extern __shared__ char smem[];
    const uint32_t sb = smem_u32(smem);
    const int t = threadIdx.x;
    const int lane = t & 31;
    const int wid  = t >> 5;
    const int wm   = wid & 3;
    const int wn   = wid >> 2;
    const int m0 = blockIdx.y * 128;
    const int n0 = blockIdx.x * 128;

    const uint32_t a_off = (uint32_t)((wm * 32 + (lane & 15)) * HROWB + (lane >> 4) * 16);
    const uint32_t b_off = (uint32_t)((lane & 15) * WROWB + ((lane >> 4) & 1) * 16 + wn * 128);

    auto load_stage = [&](int c, int s) {
        const uint32_t st = sb + (uint32_t)s * HSTAGE_B;
        const int k0 = c * HBK;
#pragma unroll
        for (int h = 0; h < 4; h++) {
            int idx = t + h * 256;
            int row = idx >> 3, cc = idx & 7;
            cpa16(st + (uint32_t)(row * HROWB + cc * 16),
                  A + (size_t)(m0 + row) * DMODEL + k0 + cc * 8);
        }
#pragma unroll
        for (int h = 0; h < 4; h++) {
            int idx = t + h * 256;
            int row = idx >> 4, cc = idx & 15;
            cpa16(st + HA_B + (uint32_t)(row * WROWB + cc * 16),
                  W + (size_t)(k0 + row) * DMODEL + n0 + cc * 8);
        }
        cpa_commit();
    };

    float acc[2][8][4];
#pragma unroll
    for (int i = 0; i < 2; i++)
#pragma unroll
        for (int j = 0; j < 8; j++)
#pragma unroll
            for (int r = 0; r < 4; r++) acc[i][j][r] = 0.f;

    load_stage(0, 0);

    for (int c = 0; c < HNCHUNK; c++) {
        if (c + 1 < HNCHUNK) {
            load_stage(c + 1, (c + 1) & 1);
            asm volatile("cp.async.wait_group 1;" ::: "memory");
        } else {
            asm volatile("cp.async.wait_group 0;" ::: "memory");
        }
        __syncthreads();

        const uint32_t st = sb + (uint32_t)(c & 1) * HSTAGE_B;
#pragma unroll
        for (int ks = 0; ks < 4; ks++) {        // 4 x K16 slabs
            uint32_t af[2][4], bf[4][4];
#pragma unroll
            for (int mt = 0; mt < 2; mt++)
                ldsm_x4(af[mt][0], af[mt][1], af[mt][2], af[mt][3],
                        st + a_off + (uint32_t)(mt * 16 * HROWB + ks * 32));
#pragma unroll
            for (int np = 0; np < 4; np++)
                ldsm_x4t(bf[np][0], bf[np][1], bf[np][2], bf[np][3],
                         st + HA_B + b_off + (uint32_t)(ks * 16 * WROWB + np * 32));
#pragma unroll
            for (int mt = 0; mt < 2; mt++)
#pragma unroll
                for (int np = 0; np < 4; np++) {
                    mma_f16(acc[mt][np * 2 + 0], af[mt], &bf[np][0]);
                    mma_f16(acc[mt][np * 2 + 1], af[mt], &bf[np][2]);
                }
        }
        __syncthreads();
    }

    const int gid = lane >> 2, tig = lane & 3;
#pragma unroll
    for (int mt = 0; mt < 2; mt++) {
        const int r0 = m0 + wm * 32 + mt * 16 + gid;
#pragma unroll
        for (int j = 0; j < 8; j++) {
            const int col = n0 + wn * 64 + j * 8 + tig * 2;
            const float bx = bias[col], by = bias[col + 1];
            float v0x = (acc[mt][j][0] + bx) * outscale;
            float v0y = (acc[mt][j][1] + by) * outscale;
            float v1x = (acc[mt][j][2] + bx) * outscale;
            float v1y = (acc[mt][j][3] + by) * outscale;
            if (Ch) {
                *(uint32_t*)&Ch[(size_t)r0 * DMODEL + col]       = packh2(v0y, v0x);
                *(uint32_t*)&Ch[(size_t)(r0 + 8) * DMODEL + col] = packh2(v1y, v1x);
            } else {
                float2 a = {v0x, v0y}, b2 = {v1x, v1y};
                *(float2*)&Cf[(size_t)r0 * DMODEL + col]       = a;
                *(float2*)&Cf[(size_t)(r0 + 8) * DMODEL + col] = b2;
            }
        }
    }
}

// ==================== flash attention 2 (fp16 mma.sync, BM=128) ====================
// CTA: 128 queries, 4 warps; warp owns 32 q-rows = 2 m16 tiles (sequential).
// KV tiles 64x64 fp16 double-buffered. Output fp16 (feeds wo GEMM directly).
#define FA_BM 128
#define FA_BN 64
#define FA_PADH 72
#define FA_ROWB (FA_PADH * 2)          // 144
#define FA_KV_B (FA_BN * FA_ROWB)      // 9216
#define FA_Q_B  (FA_BM * FA_ROWB)      // 18432
#define FA_DYN  (FA_Q_B + 4 * FA_KV_B) // 55296

__global__ __launch_bounds__(128, 2)
void fa_kernel(const __half* __restrict__ Qh, const __half* __restrict__ Kh,
               const __half* __restrict__ Vh, __half* __restrict__ Oh) {
    extern __shared__ char fsm[];
    const uint32_t sQu = smem_u32(fsm);
    const uint32_t sKu = sQu + FA_Q_B;
    const uint32_t sVu = sKu + 2 * FA_KV_B;
    __half* sQ = (__half*)fsm;

    const int t = threadIdx.x, lane = t & 31, w = t >> 5;
    const int h = blockIdx.y, b = blockIdx.z;
    const size_t qrow0 = (size_t)b * SEQ + (size_t)blockIdx.x * FA_BM;
    const size_t krow0 = (size_t)b * SEQ;
    const int hd = h * DHEAD;

    auto load_kv = [&](int kt, int s) {
#pragma unroll
        for (int i = 0; i < 4; i++) {
            int idx = t + i * 128;
            int r = idx >> 3, c = idx & 7;
            uint32_t so = (uint32_t)(s * FA_KV_B + r * FA_ROWB + c * 16);
            size_t g = (krow0 + (size_t)kt * FA_BN + r) * DMODEL + hd + c * 8;
            cpa16(sKu + so, Kh + g);
            cpa16(sVu + so, Vh + g);
        }
        cpa_commit();
    };

    load_kv(0, 0);
    for (int i = t; i < FA_BM * 8; i += 128) {
        int r = i >> 3, c = i & 7;
        *(uint4*)&sQ[r * FA_PADH + c * 8] =
            *(const uint4*)&Qh[(qrow0 + r) * DMODEL + hd + c * 8];
    }
    __syncthreads();

    // Q a-frags: 2 m-tiles x 4 K16 slabs
    uint32_t qa[2][4][4];
#pragma unroll
    for (int mt = 0; mt < 2; mt++) {
        uint32_t rb = sQu + (uint32_t)((w * 32 + mt * 16 + (lane & 15)) * FA_ROWB
                                       + ((lane >> 4) & 1) * 16);
#pragma unroll
        for (int ks = 0; ks < 4; ks++)
            ldsm_x4(qa[mt][ks][0], qa[mt][ks][1], qa[mt][ks][2], qa[mt][ks][3],
                    rb + ks * 32);
    }

    float oacc[2][8][4];
#pragma unroll
    for (int mt = 0; mt < 2; mt++)
#pragma unroll
        for (int j = 0; j < 8; j++)
#pragma unroll
            for (int r = 0; r < 4; r++) oacc[mt][j][r] = 0.f;
    float mrow[2][2] = {{-1e30f, -1e30f}, {-1e30f, -1e30f}};
    float lrow[2][2] = {{0.f, 0.f}, {0.f, 0.f}};

    const uint32_t k_off = (uint32_t)(((lane & 7) + ((lane >> 4) & 1) * 8) * FA_ROWB
                                      + ((lane >> 3) & 1) * 16);
    const uint32_t v_off = (uint32_t)((lane & 15) * FA_ROWB + ((lane >> 4) & 1) * 16);

    const int NT = SEQ / FA_BN;   // 32
    for (int kt = 0; kt < NT; kt++) {
        if (kt + 1 < NT) {
            load_kv(kt + 1, (kt + 1) & 1);
            asm volatile("cp.async.wait_group 1;" ::: "memory");
        } else {
            asm volatile("cp.async.wait_group 0;" ::: "memory");
        }
        __syncthreads();

        const uint32_t kb_ = sKu + (uint32_t)(kt & 1) * FA_KV_B;
        const uint32_t vb_ = sVu + (uint32_t)(kt & 1) * FA_KV_B;

#pragma unroll
        for (int mt = 0; mt < 2; mt++) {
            // ---- S = Q K^T (scale pre-folded into Q) ----
            float sacc[8][4];
#pragma unroll
            for (int j = 0; j < 8; j++)
#pragma unroll
                for (int r = 0; r < 4; r++) sacc[j][r] = 0.f;
#pragma unroll
            for (int ks = 0; ks < 4; ks++)
#pragma unroll
                for (int np = 0; np < 4; np++) {
                    uint32_t kb[4];
                    ldsm_x4(kb[0], kb[1], kb[2], kb[3],
                            kb_ + k_off + (uint32_t)(np * 16 * FA_ROWB + ks * 32));
                    mma_f16(sacc[np * 2 + 0], qa[mt][ks], &kb[0]);
                    mma_f16(sacc[np * 2 + 1], qa[mt][ks], &kb[2]);
                }

            // ---- online softmax ----
            float mx0 = -1e30f, mx1 = -1e30f;
#pragma unroll
            for (int j = 0; j < 8; j++) {
                mx0 = fmaxf(mx0, fmaxf(sacc[j][0], sacc[j][1]));
                mx1 = fmaxf(mx1, fmaxf(sacc[j][2], sacc[j][3]));
            }
            mx0 = fmaxf(mx0, __shfl_xor_sync(0xFFFFFFFFu, mx0, 1));
            mx0 = fmaxf(mx0, __shfl_xor_sync(0xFFFFFFFFu, mx0, 2));
            mx1 = fmaxf(mx1, __shfl_xor_sync(0xFFFFFFFFu, mx1, 1));
            mx1 = fmaxf(mx1, __shfl_xor_sync(0xFFFFFFFFu, mx1, 2));
            float mn0 = fmaxf(mrow[mt][0], mx0), mn1 = fmaxf(mrow[mt][1], mx1);
            float c0 = __expf(mrow[mt][0] - mn0), c1 = __expf(mrow[mt][1] - mn1);
            float rs0 = 0.f, rs1 = 0.f;
#pragma unroll
            for (int j = 0; j < 8; j++) {
                sacc[j][0] = __expf(sacc[j][0] - mn0);
                sacc[j][1] = __expf(sacc[j][1] - mn0);
                sacc[j][2] = __expf(sacc[j][2] - mn1);
                sacc[j][3] = __expf(sacc[j][3] - mn1);
                rs0 += sacc[j][0] + sacc[j][1];
                rs1 += sacc[j][2] + sacc[j][3];
            }
            rs0 += __shfl_xor_sync(0xFFFFFFFFu, rs0, 1);
            rs0 += __shfl_xor_sync(0xFFFFFFFFu, rs0, 2);
            rs1 += __shfl_xor_sync(0xFFFFFFFFu, rs1, 1);
            rs1 += __shfl_xor_sync(0xFFFFFFFFu, rs1, 2);
            lrow[mt][0] = lrow[mt][0] * c0 + rs0;
            lrow[mt][1] = lrow[mt][1] * c1 + rs1;
            mrow[mt][0] = mn0; mrow[mt][1] = mn1;
#pragma unroll
            for (int j = 0; j < 8; j++) {
                oacc[mt][j][0] *= c0; oacc[mt][j][1] *= c0;
                oacc[mt][j][2] *= c1; oacc[mt][j][3] *= c1;
            }

            // ---- pack P ----
            uint32_t pa[4][4];
#pragma unroll
            for (int ks = 0; ks < 4; ks++) {
                pa[ks][0] = packh2(sacc[2 * ks][1],     sacc[2 * ks][0]);
                pa[ks][1] = packh2(sacc[2 * ks][3],     sacc[2 * ks][2]);
                pa[ks][2] = packh2(sacc[2 * ks + 1][1], sacc[2 * ks + 1][0]);
                pa[ks][3] = packh2(sacc[2 * ks + 1][3], sacc[2 * ks + 1][2]);
            }

            // ---- O += P V ----
#pragma unroll
            for (int ks = 0; ks < 4; ks++)
#pragma unroll
                for (int np = 0; np < 4; np++) {
                    uint32_t vb[4];
                    ldsm_x4t(vb[0], vb[1], vb[2], vb[3],
                             vb_ + v_off + (uint32_t)(ks * 16 * FA_ROWB + np * 32));
                    mma_f16(oacc[mt][np * 2 + 0], pa[ks], &vb[0]);
                    mma_f16(oacc[mt][np * 2 + 1], pa[ks], &vb[2]);
                }
        }
        __syncthreads();
    }

    // ---- epilogue: normalize, store fp16 ----
#pragma unroll
    for (int mt = 0; mt < 2; mt++) {
        const float il0 = 1.f / lrow[mt][0], il1 = 1.f / lrow[mt][1];
        const size_t r0g = qrow0 + w * 32 + mt * 16 + (lane >> 2);
        const int colb = hd + (lane & 3) * 2;
#pragma unroll
        for (int j = 0; j < 8; j++) {
            const int col = colb + j * 8;
            *(uint32_t*)&Oh[r0g * DMODEL + col] =
                packh2(oacc[mt][j][1] * il0, oacc[mt][j][0] * il0);
            *(uint32_t*)&Oh[(r0g + 8) * DMODEL + col] =
                packh2(oacc[mt][j][3] * il1, oacc[mt][j][2] * il1);
        }
    }
}

// -------------------- launch --------------------
extern "C" void kernel_launch(void* const* d_in, const int* in_sizes, int n_in,
                              void* d_out, int out_size) {
    // metadata order: v, k, q, wq, bq, wk, bk, wv, bv, wo, bo
    const float* v  = (const float*)d_in[0];
    const float* k  = (const float*)d_in[1];
    const float* q  = (const float*)d_in[2];
    const float* wq = (const float*)d_in[3];
    const float* bq = (const float*)d_in[4];
    const float* wk = (const float*)d_in[5];
    const float* bk = (const float*)d_in[6];
    const float* wv = (const float*)d_in[7];
    const float* bv = (const float*)d_in[8];
    const float* wo = (const float*)d_in[9];
    const float* bo = (const float*)d_in[10];
    float* out = (float*)d_out;

    __half* Qh;  cudaGetSymbolAddress((void**)&Qh, g_Qh);
    __half* Kh;  cudaGetSymbolAddress((void**)&Kh, g_Kh);
    __half* Vh;  cudaGetSymbolAddress((void**)&Vh, g_Vh);
    __half* Af;  cudaGetSymbolAddress((void**)&Af, g_Af16);
    __half* Wf;  cudaGetSymbolAddress((void**)&Wf, g_Wf16);

    cudaFuncSetAttribute(gemm_f16_kernel,
                         cudaFuncAttributeMaxDynamicSharedMemorySize, HGEMM_DYN);
    cudaFuncSetAttribute(fa_kernel,
                         cudaFuncAttributeMaxDynamicSharedMemorySize, FA_DYN);

    const int N4 = MROWS * DMODEL / 4;     // activation float4s
    const int W4 = DMODEL * DMODEL / 4;    // weight float4s
    const dim3 ggrid(DMODEL / 128, MROWS / 128);   // (8, 64)
    const float qscale = 0.125f;                   // 1/sqrt(DHEAD), folded into Q

    // Q = (q @ wq + bq) * scale -> fp16
    conv_f16_kernel<<<(N4 + 255) / 256, 256>>>(q, Af, N4);
    conv_f16_kernel<<<(W4 + 255) / 256, 256>>>(wq, Wf, W4);
    gemm_f16_kernel<<<ggrid, 256, HGEMM_DYN>>>(Af, Wf, bq, qscale, Qh, nullptr);
    // K
    conv_f16_kernel<<<(N4 + 255) / 256, 256>>>(k, Af, N4);
    conv_f16_kernel<<<(W4 + 255) / 256, 256>>>(wk, Wf, W4);
    gemm_f16_kernel<<<ggrid, 256, HGEMM_DYN>>>(Af, Wf, bk, 1.0f, Kh, nullptr);
    // V
    conv_f16_kernel<<<(N4 + 255) / 256, 256>>>(v, Af, N4);
    conv_f16_kernel<<<(W4 + 255) / 256, 256>>>(wv, Wf, W4);
    gemm_f16_kernel<<<ggrid, 256, HGEMM_DYN>>>(Af, Wf, bv, 1.0f, Vh, nullptr);

    // attention -> fp16 (feeds wo GEMM directly)
    dim3 agrid(SEQ / FA_BM, NHEADS, BATCH);        // (16, 16, 4)
    fa_kernel<<<agrid, 128, FA_DYN>>>(Qh, Kh, Vh, Af);

    // out = O @ wo + bo  (single-pass fp16, fp32 out)
    conv_f16_kernel<<<(W4 + 255) / 256, 256>>>(wo, Wf, W4);
    gemm_f16_kernel<<<ggrid, 256, HGEMM_DYN>>>(Af, Wf, bo, 1.0f, nullptr, out);
}